// round 8
// baseline (speedup 1.0000x reference)
#include <cuda_runtime.h>
#include <cuda_bf16.h>
#include <math.h>
#include <stdint.h>

#define B_    4
#define L_    16
#define D_    512
#define H_    8
#define HD_   64
#define NTOK_ 1024
#define E3_   1536

// Scratch (allocation-free rule: __device__ globals)
__device__ float g_Q[B_ * H_ * NTOK_ * HD_];
__device__ __nv_bfloat16 g_Khi[B_ * H_ * NTOK_ * HD_];
__device__ __nv_bfloat16 g_Klo[B_ * H_ * NTOK_ * HD_];
__device__ __nv_bfloat16 g_Vhi[B_ * H_ * NTOK_ * HD_];
__device__ __nv_bfloat16 g_Vlo[B_ * H_ * NTOK_ * HD_];
__device__ __nv_bfloat16 g_Xhi[4096 * 512];
__device__ __nv_bfloat16 g_Xlo[4096 * 512];
__device__ __nv_bfloat16 g_Whi[1536 * 512];
__device__ __nv_bfloat16 g_Wlo[1536 * 512];

__device__ __forceinline__ uint32_t smem_u32(const void* p) {
    uint32_t a;
    asm("{ .reg .u64 t; cvta.to.shared.u64 t, %1; cvt.u32.u64 %0, t; }" : "=r"(a) : "l"(p));
    return a;
}
__device__ __forceinline__ void ldsm4(uint32_t* r, uint32_t addr) {
    asm volatile("ldmatrix.sync.aligned.m8n8.x4.shared.b16 {%0,%1,%2,%3}, [%4];"
        : "=r"(r[0]), "=r"(r[1]), "=r"(r[2]), "=r"(r[3]) : "r"(addr));
}
__device__ __forceinline__ void ldsm4t(uint32_t* r, uint32_t addr) {
    asm volatile("ldmatrix.sync.aligned.m8n8.x4.trans.shared.b16 {%0,%1,%2,%3}, [%4];"
        : "=r"(r[0]), "=r"(r[1]), "=r"(r[2]), "=r"(r[3]) : "r"(addr));
}
__device__ __forceinline__ void mma16816(float* c, const uint32_t* a, uint32_t b0, uint32_t b1) {
    asm volatile("mma.sync.aligned.m16n8k16.row.col.f32.bf16.bf16.f32 "
        "{%0,%1,%2,%3}, {%4,%5,%6,%7}, {%8,%9}, {%0,%1,%2,%3};"
        : "+f"(c[0]), "+f"(c[1]), "+f"(c[2]), "+f"(c[3])
        : "r"(a[0]), "r"(a[1]), "r"(a[2]), "r"(a[3]), "r"(b0), "r"(b1));
}
__device__ __forceinline__ uint32_t packbf2(float a, float b) {
    __nv_bfloat162 t = __floats2bfloat162_rn(a, b);
    return *reinterpret_cast<uint32_t*>(&t);
}

extern __shared__ char smem_raw[];

// ---------------------------------------------------------------------------
// Kernel 0: split X and W into bf16 (hi, lo) pairs.
// ---------------------------------------------------------------------------
#define XQUADS 524288   // 4096*512/4
#define WQUADS 196608   // 1536*512/4

__global__ __launch_bounds__(256) void split_kernel(const float* __restrict__ x,
                                                    const float* __restrict__ W) {
    int i = blockIdx.x * 256 + threadIdx.x;
    const float4* src;
    __nv_bfloat16 *hi, *lo;
    int idx;
    if (i < XQUADS) { src = (const float4*)x; hi = g_Xhi; lo = g_Xlo; idx = i; }
    else            { src = (const float4*)W; hi = g_Whi; lo = g_Wlo; idx = i - XQUADS; }
    float4 v = src[idx];
    float f[4] = {v.x, v.y, v.z, v.w};
    __nv_bfloat162* hp = (__nv_bfloat162*)hi;
    __nv_bfloat162* lp = (__nv_bfloat162*)lo;
#pragma unroll
    for (int j = 0; j < 2; j++) {
        __nv_bfloat16 h0 = __float2bfloat16_rn(f[2 * j]);
        __nv_bfloat16 h1 = __float2bfloat16_rn(f[2 * j + 1]);
        __nv_bfloat16 l0 = __float2bfloat16_rn(f[2 * j] - __bfloat162float(h0));
        __nv_bfloat16 l1 = __float2bfloat16_rn(f[2 * j + 1] - __bfloat162float(h1));
        hp[idx * 2 + j] = __halves2bfloat162(h0, h1);
        lp[idx * 2 + j] = __halves2bfloat162(l0, l1);
    }
}

// ---------------------------------------------------------------------------
// Kernel 1: QKV GEMM via bf16 mma.sync, K' = 1536.
// NEW: 4 warps, warp tile 64x64 (2x2 warp grid on 128x128 block tile),
// 4-stage cp.async ring with wait_group 2, occ 2.
// ---------------------------------------------------------------------------
#define GEMM_SMEM (8 * 8192 + 512)

__global__ __launch_bounds__(128, 2) void qkv_gemm(const float* __restrict__ te,
                                                   const float* __restrict__ Wt) {
    uint32_t aBase = smem_u32(smem_raw);
    uint32_t bBase = aBase + 4 * 8192;
    float* s_tq = (float*)(smem_raw + 8 * 8192);

    int tid = threadIdx.x;
    int m0 = blockIdx.y * 128, e0 = blockIdx.x * 128;
    int bb = m0 >> 10, l0 = (m0 >> 6) & 15, third = e0 >> 9;

    // per-thread load rows (row = tid for both A and B, 4 chunks of 16B)
    int swr = (tid >> 1) & 3;
    const __nv_bfloat16* Asrc = g_Xhi + (size_t)(m0 + tid) * 512;
    const __nv_bfloat16* Alo  = g_Xlo + (size_t)(m0 + tid) * 512;
    const __nv_bfloat16* Bsrc = g_Whi + (size_t)(e0 + tid) * 512;
    const __nv_bfloat16* Blo  = g_Wlo + (size_t)(e0 + tid) * 512;
    uint32_t dA0 = aBase + tid * 64, dB0 = bBase + tid * 64;

#define ISSUE(ki, st) do {                                                      \
    int _r = (ki) >> 4, _kb = ((ki) & 15) * 32;                                 \
    const __nv_bfloat16* _ap = (_r == 1) ? Alo : Asrc;                          \
    const __nv_bfloat16* _bp = (_r == 2) ? Blo : Bsrc;                          \
    _Pragma("unroll")                                                           \
    for (int _c = 0; _c < 4; _c++) {                                            \
        uint32_t _sw = ((_c ^ swr) << 4);                                       \
        asm volatile("cp.async.cg.shared.global [%0], [%1], 16;"                \
                     :: "r"(dA0 + (st) * 8192 + _sw), "l"(_ap + _kb + _c * 8)); \
        asm volatile("cp.async.cg.shared.global [%0], [%1], 16;"                \
                     :: "r"(dB0 + (st) * 8192 + _sw), "l"(_bp + _kb + _c * 8)); \
    }                                                                           \
    asm volatile("cp.async.commit_group;");                                     \
} while (0)

    // prefetch 3 stages, then in-block tqkv overlaps with load latency
    ISSUE(0, 0);
    ISSUE(1, 1);
    ISSUE(2, 2);

    // tqkv: s_tq[fr*64+hd] = te[bb, l0+fr, :] . Wt[third*64+hd, :]
    {
        int fr = tid >> 6, hd = tid & 63;
        const float4* tp = (const float4*)(te + (size_t)(bb * 16 + l0 + fr) * D_);
        const float4* wp = (const float4*)(Wt + (size_t)(third * 64 + hd) * D_);
        float acc = 0.f;
#pragma unroll 8
        for (int k = 0; k < 128; k++) {
            float4 a = tp[k], w = wp[k];
            acc += a.x * w.x + a.y * w.y + a.z * w.z + a.w * w.w;
        }
        s_tq[tid] = acc;
    }

    int lane = tid & 31, warp = tid >> 5;
    int wm = warp & 1, wn = warp >> 1;
    uint32_t aAddr[4]; int aXor[4];
    int rA = lane & 15, kcbA = lane >> 4;
#pragma unroll
    for (int im = 0; im < 4; im++) {
        int mr = wm * 64 + im * 16 + rA;
        aAddr[im] = aBase + mr * 64;
        aXor[im] = (mr >> 1) & 3;
    }
    uint32_t bAddr[4]; int bXor[4];
    int kcbB = (lane >> 3) & 1;
#pragma unroll
    for (int p = 0; p < 4; p++) {
        int nr = wn * 64 + p * 16 + (lane & 7) + ((lane >> 4) << 3);
        bAddr[p] = bBase + nr * 64;
        bXor[p] = (nr >> 1) & 3;
    }

    float c[4][8][4] = {};

    for (int ki = 0; ki < 48; ki++) {
        asm volatile("cp.async.wait_group 2;" ::: "memory");
        __syncthreads();
        if (ki + 3 < 48) ISSUE(ki + 3, (ki + 3) & 3);
        int cur = ki & 3;
#pragma unroll
        for (int s = 0; s < 2; s++) {
            uint32_t a[4][4];
#pragma unroll
            for (int im = 0; im < 4; im++)
                ldsm4(a[im], aAddr[im] + cur * 8192 + (((kcbA + 2 * s) ^ aXor[im]) << 4));
            uint32_t bq[4][4];
#pragma unroll
            for (int p = 0; p < 4; p++)
                ldsm4(bq[p], bAddr[p] + cur * 8192 + (((kcbB + 2 * s) ^ bXor[p]) << 4));
#pragma unroll
            for (int im = 0; im < 4; im++)
#pragma unroll
                for (int in = 0; in < 8; in++)
                    mma16816(c[im][in], a[im], bq[in >> 1][(in & 1) * 2], bq[in >> 1][(in & 1) * 2 + 1]);
        }
    }

    const float inv_scale = 0.044194173824159216f;  // 1/sqrt(512)
    int gid = lane >> 2, tig = lane & 3;
#pragma unroll
    for (int im = 0; im < 4; im++) {
#pragma unroll
        for (int hrow = 0; hrow < 2; hrow++) {
            int row = m0 + wm * 64 + im * 16 + gid + hrow * 8;
            int b = row >> 10, l = (row >> 6) & 15, nt = row & 63;
            int frl = (row >> 6) & 1;
#pragma unroll
            for (int in = 0; in < 8; in++) {
                int e = e0 + wn * 64 + in * 8 + 2 * tig;
                int h = (e >> 6) & 7, hd = e & 63;
                float v0 = c[im][in][2 * hrow + 0] + s_tq[frl * 64 + hd];
                float v1 = c[im][in][2 * hrow + 1] + s_tq[frl * 64 + hd + 1];
                size_t off = (size_t)((b * H_ + h) * NTOK_ + l * 64 + nt) * HD_ + hd;
                if (third == 0) {
                    *(float2*)(g_Q + off) = make_float2(v0 * inv_scale, v1 * inv_scale);
                } else {
                    __nv_bfloat16 h0 = __float2bfloat16_rn(v0), h1 = __float2bfloat16_rn(v1);
                    __nv_bfloat162 hv = __halves2bfloat162(h0, h1);
                    __nv_bfloat162 lv = __floats2bfloat162_rn(v0 - __bfloat162float(h0),
                                                              v1 - __bfloat162float(h1));
                    __nv_bfloat162* hiA = (third == 1) ? (__nv_bfloat162*)g_Khi : (__nv_bfloat162*)g_Vhi;
                    __nv_bfloat162* loA = (third == 1) ? (__nv_bfloat162*)g_Klo : (__nv_bfloat162*)g_Vlo;
                    hiA[off >> 1] = hv;
                    loA[off >> 1] = lv;
                }
            }
        }
    }
}

// ---------------------------------------------------------------------------
// Kernel 2: tensor-core fused attention (unchanged from round 7)
// ---------------------------------------------------------------------------
#define ATT_KV     0
#define ATT_QS     0
#define ATT_ET     17408
#define ATT_QHI    65536
#define ATT_QLO    (ATT_QHI + 8192)
#define ATT_BIAS   (ATT_QLO + 8192)
#define ATT_LIST   (ATT_BIAS + 64 * 17 * 4)
#define ATT_SMEM   (ATT_LIST + 68)

__global__ __launch_bounds__(128, 2) void attn_kernel(const int* __restrict__ pos,
                                                      const int* __restrict__ mask,
                                                      const float* __restrict__ emb,
                                                      float* __restrict__ out) {
    uint32_t sbase = smem_u32(smem_raw);
    float (*Qs)[68] = (float(*)[68])(smem_raw + ATT_QS);
    float (*Et)[68] = (float(*)[68])(smem_raw + ATT_ET);
    float (*bias)[17] = (float(*)[17])(smem_raw + ATT_BIAS);
    int* list = (int*)(smem_raw + ATT_LIST);

    int ql = (L_ - 1) - blockIdx.x;
    int h = blockIdx.y, b = blockIdx.z;
    int tid = threadIdx.x;
    int lane = tid & 31, w = tid >> 5;
    int r0 = w * 16;
    int bh = b * H_ + h;

    if (tid == 0) {
        int nvl = 0;
        const int* mrow = mask + (b * L_ + ql) * L_;
#pragma unroll
        for (int kl = 0; kl < L_; kl++)
            if (mrow[kl] != 0) list[nvl++] = kl;
        list[16] = nvl;
    }

    const float* Qg = g_Q + ((size_t)bh * NTOK_ + ql * 64) * HD_;
    for (int i = tid; i < 1024; i += 128) {
        int r = i >> 4, c = (i & 15) << 2;
        *(float4*)&Qs[r][c] = *(const float4*)(Qg + r * HD_ + c);
    }
    for (int i = tid; i < 1024; i += 128) {
        int kl = i >> 6, c = i & 63;
        int p = pos[(b * L_ + ql) * L_ + kl];
        p = min(max(p, -8), 8) + 8;
        Et[kl][c] = emb[p * HD_ + c];
    }
    __syncthreads();
    int nv = list[16];

#pragma unroll
    for (int u = 0; u < 8; u++) {
        int id = tid + u * 128;
        int r = id >> 4, kl = id & 15;
        float acc = 0.f;
        const float* qrow = Qs[r];
        const float* erow = Et[kl];
#pragma unroll 16
        for (int c = 0; c < 64; c++) acc += qrow[c] * erow[c];
        bias[r][kl] = acc;
    }

#pragma unroll
    for (int i = 0; i < 4; i++) {
        int linear = i * 128 + tid;
        int row = linear >> 3, ch = linear & 7;
        const float* qp = &Qs[row][ch * 8];
        uint32_t hi4[4], lo4[4];
#pragma unroll
        for (int j = 0; j < 4; j++) {
            float x0 = qp[2 * j], x1 = qp[2 * j + 1];
            __nv_bfloat16 h0 = __float2bfloat16_rn(x0), h1 = __float2bfloat16_rn(x1);
            hi4[j] = packbf2(__bfloat162float(h0), __bfloat162float(h1));
            lo4[j] = packbf2(x0 - __bfloat162float(h0), x1 - __bfloat162float(h1));
        }
        uint32_t soff = row * 128 + ((ch ^ (row & 7)) << 4);
        *(uint4*)(smem_raw + ATT_QHI + soff) = *(uint4*)hi4;
        *(uint4*)(smem_raw + ATT_QLO + soff) = *(uint4*)lo4;
    }
    __syncthreads();

    uint32_t qh[4][4], qlr[4][4];
    {
        int lrow = (lane & 7) + 8 * ((lane >> 3) & 1);
        int khalf = lane >> 4;
#pragma unroll
        for (int kt = 0; kt < 4; kt++) {
            int qr = r0 + lrow;
            int qc = kt * 2 + khalf;
            uint32_t off = qr * 128 + ((qc ^ (qr & 7)) << 4);
            ldsm4(qh[kt],  sbase + ATT_QHI + off);
            ldsm4(qlr[kt], sbase + ATT_QLO + off);
        }
    }

    int g4 = lane >> 2;
    float m0r = -INFINITY, m1r = -INFINITY, l0r = 0.f, l1r = 0.f;
    float O[8][4] = {};

    int klrow = (lane & 7) + 8 * (lane >> 4);
    int kchalf = (lane >> 3) & 1;
    int vlrow = (lane & 7) + 8 * ((lane >> 3) & 1);
    int vchalf = lane >> 4;

    const __nv_bfloat16* tile_src[4] = {
        g_Khi + (size_t)bh * NTOK_ * HD_, g_Klo + (size_t)bh * NTOK_ * HD_,
        g_Vhi + (size_t)bh * NTOK_ * HD_, g_Vlo + (size_t)bh * NTOK_ * HD_
    };
    const __nv_bfloat16* mysrc = tile_src[w];
    uint32_t mydst = sbase + ATT_KV + w * 8192;

#define ISSUE_FRAME(f, stage) do {                                              \
    const __nv_bfloat16* _s = mysrc + (f) * 4096;                               \
    uint32_t _d = mydst + (stage) * 32768;                                      \
    _Pragma("unroll")                                                           \
    for (int _c = 0; _c < 16; _c++) {                                           \
        int _lin = _c * 32 + lane;                                              \
        int _row = _lin >> 3, _ch = _lin & 7;                                   \
        uint32_t _da = _d + _row * 128 + ((_ch ^ (_row & 7)) << 4);             \
        asm volatile("cp.async.cg.shared.global [%0], [%1], 16;"                \
                     :: "r"(_da), "l"(_s + _row * 64 + _ch * 8));               \
    }                                                                           \
    asm volatile("cp.async.commit_group;");                                     \
} while (0)

    ISSUE_FRAME(list[0], 0);

    for (int j = 0; j < nv; j++) {
        int stage = j & 1;
        if (j + 1 < nv) {
            ISSUE_FRAME(list[j + 1], (j + 1) & 1);
            asm volatile("cp.async.wait_group 1;" ::: "memory");
        } else {
            asm volatile("cp.async.wait_group 0;" ::: "memory");
        }
        __syncthreads();
        int kl = list[j];
        uint32_t khiB = sbase + ATT_KV + stage * 32768;
        uint32_t kloB = khiB + 8192;
        uint32_t vhiB = khiB + 16384;
        uint32_t vloB = khiB + 24576;

        float S[8][4];
        float bb0 = bias[r0 + g4][kl], bb1 = bias[r0 + 8 + g4][kl];
#pragma unroll
        for (int nt = 0; nt < 8; nt++) {
            S[nt][0] = bb0; S[nt][1] = bb0; S[nt][2] = bb1; S[nt][3] = bb1;
        }
#pragma unroll
        for (int kt = 0; kt < 4; kt++) {
#pragma unroll
            for (int np = 0; np < 4; np++) {
                int nr = np * 16 + klrow;
                int kc = kt * 2 + kchalf;
                uint32_t off = nr * 128 + ((kc ^ (nr & 7)) << 4);
                uint32_t kh[4], klo2[4];
                ldsm4(kh,   khiB + off);
                ldsm4(klo2, kloB + off);
                mma16816(S[2 * np],     qh[kt],  kh[0],   kh[1]);
                mma16816(S[2 * np + 1], qh[kt],  kh[2],   kh[3]);
                mma16816(S[2 * np],     qlr[kt], kh[0],   kh[1]);
                mma16816(S[2 * np + 1], qlr[kt], kh[2],   kh[3]);
                mma16816(S[2 * np],     qh[kt],  klo2[0], klo2[1]);
                mma16816(S[2 * np + 1], qh[kt],  klo2[2], klo2[3]);
            }
        }

        float mx0 = -INFINITY, mx1 = -INFINITY;
#pragma unroll
        for (int nt = 0; nt < 8; nt++) {
            mx0 = fmaxf(mx0, fmaxf(S[nt][0], S[nt][1]));
            mx1 = fmaxf(mx1, fmaxf(S[nt][2], S[nt][3]));
        }
        mx0 = fmaxf(mx0, __shfl_xor_sync(0xffffffffu, mx0, 1));
        mx0 = fmaxf(mx0, __shfl_xor_sync(0xffffffffu, mx0, 2));
        mx1 = fmaxf(mx1, __shfl_xor_sync(0xffffffffu, mx1, 1));
        mx1 = fmaxf(mx1, __shfl_xor_sync(0xffffffffu, mx1, 2));
        float mn0 = fmaxf(m0r, mx0), mn1 = fmaxf(m1r, mx1);
        float corr0 = __expf(m0r - mn0), corr1 = __expf(m1r - mn1);
        float sum0 = 0.f, sum1 = 0.f;
#pragma unroll
        for (int nt = 0; nt < 8; nt++) {
            S[nt][0] = __expf(S[nt][0] - mn0); S[nt][1] = __expf(S[nt][1] - mn0);
            S[nt][2] = __expf(S[nt][2] - mn1); S[nt][3] = __expf(S[nt][3] - mn1);
            sum0 += S[nt][0] + S[nt][1];
            sum1 += S[nt][2] + S[nt][3];
        }
        sum0 += __shfl_xor_sync(0xffffffffu, sum0, 1);
        sum0 += __shfl_xor_sync(0xffffffffu, sum0, 2);
        sum1 += __shfl_xor_sync(0xffffffffu, sum1, 1);
        sum1 += __shfl_xor_sync(0xffffffffu, sum1, 2);
        l0r = l0r * corr0 + sum0; m0r = mn0;
        l1r = l1r * corr1 + sum1; m1r = mn1;

        uint32_t ph[4][4], pl[4][4];
#pragma unroll
        for (int kt = 0; kt < 4; kt++) {
#pragma unroll
            for (int q = 0; q < 4; q++) {
                int nt = 2 * kt + (q >> 1);
                float x0 = S[nt][(q & 1) * 2], x1 = S[nt][(q & 1) * 2 + 1];
                __nv_bfloat16 hx0 = __float2bfloat16_rn(x0), hx1 = __float2bfloat16_rn(x1);
                __nv_bfloat162 hp2 = __halves2bfloat162(hx0, hx1);
                ph[kt][q] = *(uint32_t*)&hp2;
                __nv_bfloat162 lp2 = __floats2bfloat162_rn(x0 - __bfloat162float(hx0),
                                                           x1 - __bfloat162float(hx1));
                pl[kt][q] = *(uint32_t*)&lp2;
            }
        }

#pragma unroll
        for (int nt = 0; nt < 8; nt++) {
            O[nt][0] *= corr0; O[nt][1] *= corr0; O[nt][2] *= corr1; O[nt][3] *= corr1;
        }
#pragma unroll
        for (int kt = 0; kt < 4; kt++) {
#pragma unroll
            for (int np = 0; np < 4; np++) {
                int vr = kt * 16 + vlrow;
                int vc = np * 2 + vchalf;
                uint32_t off = vr * 128 + ((vc ^ (vr & 7)) << 4);
                uint32_t vh[4], vl[4];
                ldsm4t(vh, vhiB + off);
                ldsm4t(vl, vloB + off);
                mma16816(O[2 * np],     ph[kt], vh[0], vh[1]);
                mma16816(O[2 * np + 1], ph[kt], vh[2], vh[3]);
                mma16816(O[2 * np],     pl[kt], vh[0], vh[1]);
                mma16816(O[2 * np + 1], pl[kt], vh[2], vh[3]);
                mma16816(O[2 * np],     ph[kt], vl[0], vl[1]);
                mma16816(O[2 * np + 1], ph[kt], vl[2], vl[3]);
            }
        }
        __syncthreads();
    }

    float inv0 = 1.f / l0r, inv1 = 1.f / l1r;
    int ra = ql * 64 + r0 + g4;
    int colb = h * HD_ + 2 * (lane & 3);
    float* ob = out + (size_t)((b * L_) * 64 + ra) * D_ + colb;
#pragma unroll
    for (int nt = 0; nt < 8; nt++) {
        *(float2*)(ob + nt * 8)          = make_float2(O[nt][0] * inv0, O[nt][1] * inv0);
        *(float2*)(ob + 8 * D_ + nt * 8) = make_float2(O[nt][2] * inv1, O[nt][3] * inv1);
    }
}

// ---------------------------------------------------------------------------
extern "C" void kernel_launch(void* const* d_in, const int* in_sizes, int n_in,
                              void* d_out, int out_size) {
    const float* x    = (const float*)d_in[0];
    const float* te   = (const float*)d_in[1];
    const int*   pos  = (const int*)d_in[2];
    const int*   mask = (const int*)d_in[3];
    const float* Wqkv = (const float*)d_in[4];
    const float* Wt   = (const float*)d_in[5];
    const float* emb  = (const float*)d_in[6];
    float* out = (float*)d_out;

    cudaFuncSetAttribute(qkv_gemm, cudaFuncAttributeMaxDynamicSharedMemorySize, GEMM_SMEM);
    cudaFuncSetAttribute(attn_kernel, cudaFuncAttributeMaxDynamicSharedMemorySize, ATT_SMEM);

    split_kernel<<<(XQUADS + WQUADS) / 256, 256>>>(x, Wqkv);
    qkv_gemm<<<dim3(E3_ / 128, 4096 / 128), 128, GEMM_SMEM>>>(te, Wt);
    attn_kernel<<<dim3(L_, H_, B_), 128, ATT_SMEM>>>(pos, mask, emb, out);
}

// round 9
// speedup vs baseline: 1.3087x; 1.3087x over previous
#include <cuda_runtime.h>
#include <cuda_bf16.h>
#include <math.h>
#include <stdint.h>

#define B_    4
#define L_    16
#define D_    512
#define H_    8
#define HD_   64
#define NTOK_ 1024
#define E3_   1536

// Scratch (allocation-free rule: __device__ globals)
__device__ float g_Q[B_ * H_ * NTOK_ * HD_];
__device__ __nv_bfloat16 g_Khi[B_ * H_ * NTOK_ * HD_];
__device__ __nv_bfloat16 g_Klo[B_ * H_ * NTOK_ * HD_];
__device__ __nv_bfloat16 g_Vhi[B_ * H_ * NTOK_ * HD_];
__device__ __nv_bfloat16 g_Vlo[B_ * H_ * NTOK_ * HD_];
__device__ __nv_bfloat16 g_Xhi[4096 * 512];
__device__ __nv_bfloat16 g_Xlo[4096 * 512];
__device__ __nv_bfloat16 g_Whi[1536 * 512];
__device__ __nv_bfloat16 g_Wlo[1536 * 512];

__device__ __forceinline__ uint32_t smem_u32(const void* p) {
    uint32_t a;
    asm("{ .reg .u64 t; cvta.to.shared.u64 t, %1; cvt.u32.u64 %0, t; }" : "=r"(a) : "l"(p));
    return a;
}
__device__ __forceinline__ void ldsm4(uint32_t* r, uint32_t addr) {
    asm volatile("ldmatrix.sync.aligned.m8n8.x4.shared.b16 {%0,%1,%2,%3}, [%4];"
        : "=r"(r[0]), "=r"(r[1]), "=r"(r[2]), "=r"(r[3]) : "r"(addr));
}
__device__ __forceinline__ void ldsm4t(uint32_t* r, uint32_t addr) {
    asm volatile("ldmatrix.sync.aligned.m8n8.x4.trans.shared.b16 {%0,%1,%2,%3}, [%4];"
        : "=r"(r[0]), "=r"(r[1]), "=r"(r[2]), "=r"(r[3]) : "r"(addr));
}
__device__ __forceinline__ void mma16816(float* c, const uint32_t* a, uint32_t b0, uint32_t b1) {
    asm volatile("mma.sync.aligned.m16n8k16.row.col.f32.bf16.bf16.f32 "
        "{%0,%1,%2,%3}, {%4,%5,%6,%7}, {%8,%9}, {%0,%1,%2,%3};"
        : "+f"(c[0]), "+f"(c[1]), "+f"(c[2]), "+f"(c[3])
        : "r"(a[0]), "r"(a[1]), "r"(a[2]), "r"(a[3]), "r"(b0), "r"(b1));
}
__device__ __forceinline__ uint32_t packbf2(float a, float b) {
    __nv_bfloat162 t = __floats2bfloat162_rn(a, b);
    return *reinterpret_cast<uint32_t*>(&t);
}

extern __shared__ char smem_raw[];

// ---------------------------------------------------------------------------
// Kernel 0: split X and W into bf16 (hi, lo) pairs.
// ---------------------------------------------------------------------------
#define XQUADS 524288   // 4096*512/4
#define WQUADS 196608   // 1536*512/4

__global__ __launch_bounds__(256) void split_kernel(const float* __restrict__ x,
                                                    const float* __restrict__ W) {
    int i = blockIdx.x * 256 + threadIdx.x;
    const float4* src;
    __nv_bfloat16 *hi, *lo;
    int idx;
    if (i < XQUADS) { src = (const float4*)x; hi = g_Xhi; lo = g_Xlo; idx = i; }
    else            { src = (const float4*)W; hi = g_Whi; lo = g_Wlo; idx = i - XQUADS; }
    float4 v = src[idx];
    float f[4] = {v.x, v.y, v.z, v.w};
    __nv_bfloat162* hp = (__nv_bfloat162*)hi;
    __nv_bfloat162* lp = (__nv_bfloat162*)lo;
#pragma unroll
    for (int j = 0; j < 2; j++) {
        __nv_bfloat16 h0 = __float2bfloat16_rn(f[2 * j]);
        __nv_bfloat16 h1 = __float2bfloat16_rn(f[2 * j + 1]);
        __nv_bfloat16 l0 = __float2bfloat16_rn(f[2 * j] - __bfloat162float(h0));
        __nv_bfloat16 l1 = __float2bfloat16_rn(f[2 * j + 1] - __bfloat162float(h1));
        hp[idx * 2 + j] = __halves2bfloat162(h0, h1);
        lp[idx * 2 + j] = __halves2bfloat162(l0, l1);
    }
}

// ---------------------------------------------------------------------------
// Kernel 1: QKV GEMM via bf16 mma.sync, K' = 1536.
// Round-7 structure (256 threads, 8 warps 2m x 4n, warp tile 64x32),
// NEW: 6-stage cp.async ring, TWO k-chunks consumed per barrier (24 iters).
// Accumulation order per output element identical to round 7.
// ---------------------------------------------------------------------------
#define GEMM_SMEM (12 * 8192 + 512)

__global__ __launch_bounds__(256, 2) void qkv_gemm(const float* __restrict__ te,
                                                   const float* __restrict__ Wt) {
    uint32_t aBase = smem_u32(smem_raw);
    uint32_t bBase = aBase + 6 * 8192;
    float* s_tq = (float*)(smem_raw + 12 * 8192);

    int tid = threadIdx.x;
    int m0 = blockIdx.y * 128, e0 = blockIdx.x * 128;
    int bb = m0 >> 10, l0 = (m0 >> 6) & 15, third = e0 >> 9;

    int mld = tid >> 1;
    int kc0 = (tid & 1) * 2;
    int swm = (mld >> 1) & 3;
    uint32_t dA0 = aBase + mld * 64, dB0 = bBase + mld * 64;
    const __nv_bfloat16* Asrc = g_Xhi + (size_t)(m0 + mld) * 512;
    const __nv_bfloat16* Alo  = g_Xlo + (size_t)(m0 + mld) * 512;
    const __nv_bfloat16* Bsrc = g_Whi + (size_t)(e0 + mld) * 512;
    const __nv_bfloat16* Blo  = g_Wlo + (size_t)(e0 + mld) * 512;

#define ISSUE(ki, st) do {                                                      \
    int _r = (ki) >> 4, _kb = ((ki) & 15) * 32;                                 \
    const __nv_bfloat16* _ap = (_r == 1) ? Alo : Asrc;                          \
    const __nv_bfloat16* _bp = (_r == 2) ? Blo : Bsrc;                          \
    _Pragma("unroll")                                                           \
    for (int _j = 0; _j < 2; _j++) {                                            \
        int _kc = kc0 + _j;                                                     \
        const void* _sa = _ap + _kb + _kc * 8;                                  \
        const void* _sb = _bp + _kb + _kc * 8;                                  \
        uint32_t _da = dA0 + (st) * 8192 + (((_kc) ^ swm) << 4);                \
        uint32_t _db = dB0 + (st) * 8192 + (((_kc) ^ swm) << 4);                \
        asm volatile("cp.async.cg.shared.global [%0], [%1], 16;" :: "r"(_da), "l"(_sa)); \
        asm volatile("cp.async.cg.shared.global [%0], [%1], 16;" :: "r"(_db), "l"(_sb)); \
    }                                                                           \
    asm volatile("cp.async.commit_group;");                                     \
} while (0)

    // prefetch 4 chunks into stages 0..3
    ISSUE(0, 0);
    ISSUE(1, 1);
    ISSUE(2, 2);
    ISSUE(3, 3);

    // in-block tqkv overlaps with prefetch latency
    {
        int outi = tid >> 1, half = tid & 1;
        int fr = outi >> 6, hd = outi & 63;
        const float4* tp = (const float4*)(te + (size_t)(bb * 16 + l0 + fr) * D_) + half * 64;
        const float4* wp = (const float4*)(Wt + (size_t)(third * 64 + hd) * D_) + half * 64;
        float acc = 0.f;
#pragma unroll 8
        for (int k = 0; k < 64; k++) {
            float4 a = tp[k], w = wp[k];
            acc += a.x * w.x + a.y * w.y + a.z * w.z + a.w * w.w;
        }
        acc += __shfl_xor_sync(0xffffffffu, acc, 1);
        if (!half) s_tq[outi] = acc;
    }

    int lane = tid & 31, warp = tid >> 5;
    int wm = warp & 1, wn = warp >> 1;
    uint32_t aAddr[4]; int aXor[4];
    int rA = lane & 15, kcbA = lane >> 4;
#pragma unroll
    for (int im = 0; im < 4; im++) {
        int mr = wm * 64 + im * 16 + rA;
        aAddr[im] = aBase + mr * 64;
        aXor[im] = (mr >> 1) & 3;
    }
    uint32_t bAddr[2]; int bXor[2];
    int kcbB = (lane >> 3) & 1;
#pragma unroll
    for (int p = 0; p < 2; p++) {
        int nr = wn * 32 + p * 16 + (lane & 7) + ((lane >> 4) << 3);
        bAddr[p] = bBase + nr * 64;
        bXor[p] = (nr >> 1) & 3;
    }

    float c[4][4][4] = {};

    for (int it = 0; it < 24; it++) {
        if (it < 23) {
            asm volatile("cp.async.wait_group 2;" ::: "memory");
        } else {
            asm volatile("cp.async.wait_group 0;" ::: "memory");
        }
        __syncthreads();
        int k0 = 2 * it;
        if (k0 + 4 < 48) ISSUE(k0 + 4, (k0 + 4) % 6);
        if (k0 + 5 < 48) ISSUE(k0 + 5, (k0 + 5) % 6);
#pragma unroll
        for (int half = 0; half < 2; half++) {
            int cur = (k0 + half) % 6;
#pragma unroll
            for (int s = 0; s < 2; s++) {
                uint32_t a[4][4];
#pragma unroll
                for (int im = 0; im < 4; im++)
                    ldsm4(a[im], aAddr[im] + cur * 8192 + (((kcbA + 2 * s) ^ aXor[im]) << 4));
                uint32_t bq[2][4];
#pragma unroll
                for (int p = 0; p < 2; p++)
                    ldsm4(bq[p], bAddr[p] + cur * 8192 + (((kcbB + 2 * s) ^ bXor[p]) << 4));
#pragma unroll
                for (int im = 0; im < 4; im++)
#pragma unroll
                    for (int in = 0; in < 4; in++)
                        mma16816(c[im][in], a[im], bq[in >> 1][(in & 1) * 2], bq[in >> 1][(in & 1) * 2 + 1]);
            }
        }
    }

    const float inv_scale = 0.044194173824159216f;  // 1/sqrt(512)
    int gid = lane >> 2, tig = lane & 3;
#pragma unroll
    for (int im = 0; im < 4; im++) {
#pragma unroll
        for (int hrow = 0; hrow < 2; hrow++) {
            int row = m0 + wm * 64 + im * 16 + gid + hrow * 8;
            int b = row >> 10, l = (row >> 6) & 15, nt = row & 63;
            int frl = (row >> 6) & 1;
#pragma unroll
            for (int in = 0; in < 4; in++) {
                int e = e0 + wn * 32 + in * 8 + 2 * tig;
                int h = (e >> 6) & 7, hd = e & 63;
                float v0 = c[im][in][2 * hrow + 0] + s_tq[frl * 64 + hd];
                float v1 = c[im][in][2 * hrow + 1] + s_tq[frl * 64 + hd + 1];
                size_t off = (size_t)((b * H_ + h) * NTOK_ + l * 64 + nt) * HD_ + hd;
                if (third == 0) {
                    *(float2*)(g_Q + off) = make_float2(v0 * inv_scale, v1 * inv_scale);
                } else {
                    __nv_bfloat16 h0 = __float2bfloat16_rn(v0), h1 = __float2bfloat16_rn(v1);
                    __nv_bfloat162 hv = __halves2bfloat162(h0, h1);
                    __nv_bfloat162 lv = __floats2bfloat162_rn(v0 - __bfloat162float(h0),
                                                              v1 - __bfloat162float(h1));
                    __nv_bfloat162* hiA = (third == 1) ? (__nv_bfloat162*)g_Khi : (__nv_bfloat162*)g_Vhi;
                    __nv_bfloat162* loA = (third == 1) ? (__nv_bfloat162*)g_Klo : (__nv_bfloat162*)g_Vlo;
                    hiA[off >> 1] = hv;
                    loA[off >> 1] = lv;
                }
            }
        }
    }
}

// ---------------------------------------------------------------------------
// Kernel 2: tensor-core fused attention (round-7 exact — known good)
// ---------------------------------------------------------------------------
#define ATT_KV     0
#define ATT_QS     0
#define ATT_ET     17408
#define ATT_QHI    65536
#define ATT_QLO    (ATT_QHI + 8192)
#define ATT_BIAS   (ATT_QLO + 8192)
#define ATT_LIST   (ATT_BIAS + 64 * 17 * 4)
#define ATT_SMEM   (ATT_LIST + 68)

__global__ __launch_bounds__(128, 2) void attn_kernel(const int* __restrict__ pos,
                                                      const int* __restrict__ mask,
                                                      const float* __restrict__ emb,
                                                      float* __restrict__ out) {
    uint32_t sbase = smem_u32(smem_raw);
    float (*Qs)[68] = (float(*)[68])(smem_raw + ATT_QS);
    float (*Et)[68] = (float(*)[68])(smem_raw + ATT_ET);
    float (*bias)[17] = (float(*)[17])(smem_raw + ATT_BIAS);
    int* list = (int*)(smem_raw + ATT_LIST);

    int ql = (L_ - 1) - blockIdx.x;
    int h = blockIdx.y, b = blockIdx.z;
    int tid = threadIdx.x;
    int lane = tid & 31, w = tid >> 5;
    int r0 = w * 16;
    int bh = b * H_ + h;

    if (tid == 0) {
        int nvl = 0;
        const int* mrow = mask + (b * L_ + ql) * L_;
#pragma unroll
        for (int kl = 0; kl < L_; kl++)
            if (mrow[kl] != 0) list[nvl++] = kl;
        list[16] = nvl;
    }

    const float* Qg = g_Q + ((size_t)bh * NTOK_ + ql * 64) * HD_;
    for (int i = tid; i < 1024; i += 128) {
        int r = i >> 4, c = (i & 15) << 2;
        *(float4*)&Qs[r][c] = *(const float4*)(Qg + r * HD_ + c);
    }
    for (int i = tid; i < 1024; i += 128) {
        int kl = i >> 6, c = i & 63;
        int p = pos[(b * L_ + ql) * L_ + kl];
        p = min(max(p, -8), 8) + 8;
        Et[kl][c] = emb[p * HD_ + c];
    }
    __syncthreads();
    int nv = list[16];

#pragma unroll
    for (int u = 0; u < 8; u++) {
        int id = tid + u * 128;
        int r = id >> 4, kl = id & 15;
        float acc = 0.f;
        const float* qrow = Qs[r];
        const float* erow = Et[kl];
#pragma unroll 16
        for (int c = 0; c < 64; c++) acc += qrow[c] * erow[c];
        bias[r][kl] = acc;
    }

#pragma unroll
    for (int i = 0; i < 4; i++) {
        int linear = i * 128 + tid;
        int row = linear >> 3, ch = linear & 7;
        const float* qp = &Qs[row][ch * 8];
        uint32_t hi4[4], lo4[4];
#pragma unroll
        for (int j = 0; j < 4; j++) {
            float x0 = qp[2 * j], x1 = qp[2 * j + 1];
            __nv_bfloat16 h0 = __float2bfloat16_rn(x0), h1 = __float2bfloat16_rn(x1);
            hi4[j] = packbf2(__bfloat162float(h0), __bfloat162float(h1));
            lo4[j] = packbf2(x0 - __bfloat162float(h0), x1 - __bfloat162float(h1));
        }
        uint32_t soff = row * 128 + ((ch ^ (row & 7)) << 4);
        *(uint4*)(smem_raw + ATT_QHI + soff) = *(uint4*)hi4;
        *(uint4*)(smem_raw + ATT_QLO + soff) = *(uint4*)lo4;
    }
    __syncthreads();

    uint32_t qh[4][4], qlr[4][4];
    {
        int lrow = (lane & 7) + 8 * ((lane >> 3) & 1);
        int khalf = lane >> 4;
#pragma unroll
        for (int kt = 0; kt < 4; kt++) {
            int qr = r0 + lrow;
            int qc = kt * 2 + khalf;
            uint32_t off = qr * 128 + ((qc ^ (qr & 7)) << 4);
            ldsm4(qh[kt],  sbase + ATT_QHI + off);
            ldsm4(qlr[kt], sbase + ATT_QLO + off);
        }
    }

    int g4 = lane >> 2;
    float m0r = -INFINITY, m1r = -INFINITY, l0r = 0.f, l1r = 0.f;
    float O[8][4] = {};

    int klrow = (lane & 7) + 8 * (lane >> 4);
    int kchalf = (lane >> 3) & 1;
    int vlrow = (lane & 7) + 8 * ((lane >> 3) & 1);
    int vchalf = lane >> 4;

    const __nv_bfloat16* tile_src[4] = {
        g_Khi + (size_t)bh * NTOK_ * HD_, g_Klo + (size_t)bh * NTOK_ * HD_,
        g_Vhi + (size_t)bh * NTOK_ * HD_, g_Vlo + (size_t)bh * NTOK_ * HD_
    };
    const __nv_bfloat16* mysrc = tile_src[w];
    uint32_t mydst = sbase + ATT_KV + w * 8192;

#define ISSUE_FRAME(f, stage) do {                                              \
    const __nv_bfloat16* _s = mysrc + (f) * 4096;                               \
    uint32_t _d = mydst + (stage) * 32768;                                      \
    _Pragma("unroll")                                                           \
    for (int _c = 0; _c < 16; _c++) {                                           \
        int _lin = _c * 32 + lane;                                              \
        int _row = _lin >> 3, _ch = _lin & 7;                                   \
        uint32_t _da = _d + _row * 128 + ((_ch ^ (_row & 7)) << 4);             \
        asm volatile("cp.async.cg.shared.global [%0], [%1], 16;"                \
                     :: "r"(_da), "l"(_s + _row * 64 + _ch * 8));               \
    }                                                                           \
    asm volatile("cp.async.commit_group;");                                     \
} while (0)

    ISSUE_FRAME(list[0], 0);

    for (int j = 0; j < nv; j++) {
        int stage = j & 1;
        if (j + 1 < nv) {
            ISSUE_FRAME(list[j + 1], (j + 1) & 1);
            asm volatile("cp.async.wait_group 1;" ::: "memory");
        } else {
            asm volatile("cp.async.wait_group 0;" ::: "memory");
        }
        __syncthreads();
        int kl = list[j];
        uint32_t khiB = sbase + ATT_KV + stage * 32768;
        uint32_t kloB = khiB + 8192;
        uint32_t vhiB = khiB + 16384;
        uint32_t vloB = khiB + 24576;

        float S[8][4];
        float bb0 = bias[r0 + g4][kl], bb1 = bias[r0 + 8 + g4][kl];
#pragma unroll
        for (int nt = 0; nt < 8; nt++) {
            S[nt][0] = bb0; S[nt][1] = bb0; S[nt][2] = bb1; S[nt][3] = bb1;
        }
#pragma unroll
        for (int kt = 0; kt < 4; kt++) {
#pragma unroll
            for (int np = 0; np < 4; np++) {
                int nr = np * 16 + klrow;
                int kc = kt * 2 + kchalf;
                uint32_t off = nr * 128 + ((kc ^ (nr & 7)) << 4);
                uint32_t kh[4], klo2[4];
                ldsm4(kh,   khiB + off);
                ldsm4(klo2, kloB + off);
                mma16816(S[2 * np],     qh[kt],  kh[0],   kh[1]);
                mma16816(S[2 * np + 1], qh[kt],  kh[2],   kh[3]);
                mma16816(S[2 * np],     qlr[kt], kh[0],   kh[1]);
                mma16816(S[2 * np + 1], qlr[kt], kh[2],   kh[3]);
                mma16816(S[2 * np],     qh[kt],  klo2[0], klo2[1]);
                mma16816(S[2 * np + 1], qh[kt],  klo2[2], klo2[3]);
            }
        }

        float mx0 = -INFINITY, mx1 = -INFINITY;
#pragma unroll
        for (int nt = 0; nt < 8; nt++) {
            mx0 = fmaxf(mx0, fmaxf(S[nt][0], S[nt][1]));
            mx1 = fmaxf(mx1, fmaxf(S[nt][2], S[nt][3]));
        }
        mx0 = fmaxf(mx0, __shfl_xor_sync(0xffffffffu, mx0, 1));
        mx0 = fmaxf(mx0, __shfl_xor_sync(0xffffffffu, mx0, 2));
        mx1 = fmaxf(mx1, __shfl_xor_sync(0xffffffffu, mx1, 1));
        mx1 = fmaxf(mx1, __shfl_xor_sync(0xffffffffu, mx1, 2));
        float mn0 = fmaxf(m0r, mx0), mn1 = fmaxf(m1r, mx1);
        float corr0 = __expf(m0r - mn0), corr1 = __expf(m1r - mn1);
        float sum0 = 0.f, sum1 = 0.f;
#pragma unroll
        for (int nt = 0; nt < 8; nt++) {
            S[nt][0] = __expf(S[nt][0] - mn0); S[nt][1] = __expf(S[nt][1] - mn0);
            S[nt][2] = __expf(S[nt][2] - mn1); S[nt][3] = __expf(S[nt][3] - mn1);
            sum0 += S[nt][0] + S[nt][1];
            sum1 += S[nt][2] + S[nt][3];
        }
        sum0 += __shfl_xor_sync(0xffffffffu, sum0, 1);
        sum0 += __shfl_xor_sync(0xffffffffu, sum0, 2);
        sum1 += __shfl_xor_sync(0xffffffffu, sum1, 1);
        sum1 += __shfl_xor_sync(0xffffffffu, sum1, 2);
        l0r = l0r * corr0 + sum0; m0r = mn0;
        l1r = l1r * corr1 + sum1; m1r = mn1;

        uint32_t ph[4][4], pl[4][4];
#pragma unroll
        for (int kt = 0; kt < 4; kt++) {
#pragma unroll
            for (int q = 0; q < 4; q++) {
                int nt = 2 * kt + (q >> 1);
                float x0 = S[nt][(q & 1) * 2], x1 = S[nt][(q & 1) * 2 + 1];
                __nv_bfloat16 hx0 = __float2bfloat16_rn(x0), hx1 = __float2bfloat16_rn(x1);
                __nv_bfloat162 hp2 = __halves2bfloat162(hx0, hx1);
                ph[kt][q] = *(uint32_t*)&hp2;
                __nv_bfloat162 lp2 = __floats2bfloat162_rn(x0 - __bfloat162float(hx0),
                                                           x1 - __bfloat162float(hx1));
                pl[kt][q] = *(uint32_t*)&lp2;
            }
        }

#pragma unroll
        for (int nt = 0; nt < 8; nt++) {
            O[nt][0] *= corr0; O[nt][1] *= corr0; O[nt][2] *= corr1; O[nt][3] *= corr1;
        }
#pragma unroll
        for (int kt = 0; kt < 4; kt++) {
#pragma unroll
            for (int np = 0; np < 4; np++) {
                int vr = kt * 16 + vlrow;
                int vc = np * 2 + vchalf;
                uint32_t off = vr * 128 + ((vc ^ (vr & 7)) << 4);
                uint32_t vh[4], vl[4];
                ldsm4t(vh, vhiB + off);
                ldsm4t(vl, vloB + off);
                mma16816(O[2 * np],     ph[kt], vh[0], vh[1]);
                mma16816(O[2 * np + 1], ph[kt], vh[2], vh[3]);
                mma16816(O[2 * np],     pl[kt], vh[0], vh[1]);
                mma16816(O[2 * np + 1], pl[kt], vh[2], vh[3]);
                mma16816(O[2 * np],     ph[kt], vl[0], vl[1]);
                mma16816(O[2 * np + 1], ph[kt], vl[2], vl[3]);
            }
        }
        __syncthreads();
    }

    float inv0 = 1.f / l0r, inv1 = 1.f / l1r;
    int ra = ql * 64 + r0 + g4;
    int colb = h * HD_ + 2 * (lane & 3);
    float* ob = out + (size_t)((b * L_) * 64 + ra) * D_ + colb;
#pragma unroll
    for (int nt = 0; nt < 8; nt++) {
        *(float2*)(ob + nt * 8)          = make_float2(O[nt][0] * inv0, O[nt][1] * inv0);
        *(float2*)(ob + 8 * D_ + nt * 8) = make_float2(O[nt][2] * inv1, O[nt][3] * inv1);
    }
}

// ---------------------------------------------------------------------------
extern "C" void kernel_launch(void* const* d_in, const int* in_sizes, int n_in,
                              void* d_out, int out_size) {
    const float* x    = (const float*)d_in[0];
    const float* te   = (const float*)d_in[1];
    const int*   pos  = (const int*)d_in[2];
    const int*   mask = (const int*)d_in[3];
    const float* Wqkv = (const float*)d_in[4];
    const float* Wt   = (const float*)d_in[5];
    const float* emb  = (const float*)d_in[6];
    float* out = (float*)d_out;

    cudaFuncSetAttribute(qkv_gemm, cudaFuncAttributeMaxDynamicSharedMemorySize, GEMM_SMEM);
    cudaFuncSetAttribute(attn_kernel, cudaFuncAttributeMaxDynamicSharedMemorySize, ATT_SMEM);

    split_kernel<<<(XQUADS + WQUADS) / 256, 256>>>(x, Wqkv);
    qkv_gemm<<<dim3(E3_ / 128, 4096 / 128), 256, GEMM_SMEM>>>(te, Wt);
    attn_kernel<<<dim3(L_, H_, B_), 128, ATT_SMEM>>>(pos, mask, emb, out);
}

// round 10
// speedup vs baseline: 1.3189x; 1.0078x over previous
#include <cuda_runtime.h>
#include <cuda_bf16.h>
#include <math.h>
#include <stdint.h>

#define B_    4
#define L_    16
#define D_    512
#define H_    8
#define HD_   64
#define NTOK_ 1024
#define E3_   1536

// Scratch (allocation-free rule: __device__ globals)
__device__ float g_Q[B_ * H_ * NTOK_ * HD_];
__device__ __nv_bfloat16 g_Khi[B_ * H_ * NTOK_ * HD_];
__device__ __nv_bfloat16 g_Klo[B_ * H_ * NTOK_ * HD_];
__device__ __nv_bfloat16 g_Vhi[B_ * H_ * NTOK_ * HD_];
__device__ __nv_bfloat16 g_Vlo[B_ * H_ * NTOK_ * HD_];
__device__ __nv_bfloat16 g_Xhi[4096 * 512];
__device__ __nv_bfloat16 g_Xlo[4096 * 512];
__device__ __nv_bfloat16 g_Whi[1536 * 512];
__device__ __nv_bfloat16 g_Wlo[1536 * 512];

__device__ __forceinline__ uint32_t smem_u32(const void* p) {
    uint32_t a;
    asm("{ .reg .u64 t; cvta.to.shared.u64 t, %1; cvt.u32.u64 %0, t; }" : "=r"(a) : "l"(p));
    return a;
}
__device__ __forceinline__ void ldsm4(uint32_t* r, uint32_t addr) {
    asm volatile("ldmatrix.sync.aligned.m8n8.x4.shared.b16 {%0,%1,%2,%3}, [%4];"
        : "=r"(r[0]), "=r"(r[1]), "=r"(r[2]), "=r"(r[3]) : "r"(addr));
}
__device__ __forceinline__ void ldsm4t(uint32_t* r, uint32_t addr) {
    asm volatile("ldmatrix.sync.aligned.m8n8.x4.trans.shared.b16 {%0,%1,%2,%3}, [%4];"
        : "=r"(r[0]), "=r"(r[1]), "=r"(r[2]), "=r"(r[3]) : "r"(addr));
}
__device__ __forceinline__ void mma16816(float* c, const uint32_t* a, uint32_t b0, uint32_t b1) {
    asm volatile("mma.sync.aligned.m16n8k16.row.col.f32.bf16.bf16.f32 "
        "{%0,%1,%2,%3}, {%4,%5,%6,%7}, {%8,%9}, {%0,%1,%2,%3};"
        : "+f"(c[0]), "+f"(c[1]), "+f"(c[2]), "+f"(c[3])
        : "r"(a[0]), "r"(a[1]), "r"(a[2]), "r"(a[3]), "r"(b0), "r"(b1));
}
__device__ __forceinline__ uint32_t packbf2(float a, float b) {
    __nv_bfloat162 t = __floats2bfloat162_rn(a, b);
    return *reinterpret_cast<uint32_t*>(&t);
}

extern __shared__ char smem_raw[];

// ---------------------------------------------------------------------------
// Kernel 0: split X and W into bf16 (hi, lo) pairs.
// ---------------------------------------------------------------------------
#define XQUADS 524288   // 4096*512/4
#define WQUADS 196608   // 1536*512/4

__global__ __launch_bounds__(256) void split_kernel(const float* __restrict__ x,
                                                    const float* __restrict__ W) {
    int i = blockIdx.x * 256 + threadIdx.x;
    const float4* src;
    __nv_bfloat16 *hi, *lo;
    int idx;
    if (i < XQUADS) { src = (const float4*)x; hi = g_Xhi; lo = g_Xlo; idx = i; }
    else            { src = (const float4*)W; hi = g_Whi; lo = g_Wlo; idx = i - XQUADS; }
    float4 v = src[idx];
    float f[4] = {v.x, v.y, v.z, v.w};
    __nv_bfloat162* hp = (__nv_bfloat162*)hi;
    __nv_bfloat162* lp = (__nv_bfloat162*)lo;
#pragma unroll
    for (int j = 0; j < 2; j++) {
        __nv_bfloat16 h0 = __float2bfloat16_rn(f[2 * j]);
        __nv_bfloat16 h1 = __float2bfloat16_rn(f[2 * j + 1]);
        __nv_bfloat16 l0 = __float2bfloat16_rn(f[2 * j] - __bfloat162float(h0));
        __nv_bfloat16 l1 = __float2bfloat16_rn(f[2 * j + 1] - __bfloat162float(h1));
        hp[idx * 2 + j] = __halves2bfloat162(h0, h1);
        lp[idx * 2 + j] = __halves2bfloat162(l0, l1);
    }
}

// ---------------------------------------------------------------------------
// Kernel 1: QKV GEMM via bf16 mma.sync, K' = 1536.
// r9 mainloop (6-stage ring, 2 chunks/barrier) + NEW coalesced smem-staged
// epilogue (identical arithmetic, 100% store sector efficiency).
// ---------------------------------------------------------------------------
#define GEMM_SMEM (12 * 8192 + 512)

__global__ __launch_bounds__(256, 2) void qkv_gemm(const float* __restrict__ te,
                                                   const float* __restrict__ Wt) {
    uint32_t aBase = smem_u32(smem_raw);
    uint32_t bBase = aBase + 6 * 8192;
    float* s_tq = (float*)(smem_raw + 12 * 8192);

    int tid = threadIdx.x;
    int m0 = blockIdx.y * 128, e0 = blockIdx.x * 128;
    int bb = m0 >> 10, l0 = (m0 >> 6) & 15, third = e0 >> 9;

    int mld = tid >> 1;
    int kc0 = (tid & 1) * 2;
    int swm = (mld >> 1) & 3;
    uint32_t dA0 = aBase + mld * 64, dB0 = bBase + mld * 64;
    const __nv_bfloat16* Asrc = g_Xhi + (size_t)(m0 + mld) * 512;
    const __nv_bfloat16* Alo  = g_Xlo + (size_t)(m0 + mld) * 512;
    const __nv_bfloat16* Bsrc = g_Whi + (size_t)(e0 + mld) * 512;
    const __nv_bfloat16* Blo  = g_Wlo + (size_t)(e0 + mld) * 512;

#define ISSUE(ki, st) do {                                                      \
    int _r = (ki) >> 4, _kb = ((ki) & 15) * 32;                                 \
    const __nv_bfloat16* _ap = (_r == 1) ? Alo : Asrc;                          \
    const __nv_bfloat16* _bp = (_r == 2) ? Blo : Bsrc;                          \
    _Pragma("unroll")                                                           \
    for (int _j = 0; _j < 2; _j++) {                                            \
        int _kc = kc0 + _j;                                                     \
        const void* _sa = _ap + _kb + _kc * 8;                                  \
        const void* _sb = _bp + _kb + _kc * 8;                                  \
        uint32_t _da = dA0 + (st) * 8192 + (((_kc) ^ swm) << 4);                \
        uint32_t _db = dB0 + (st) * 8192 + (((_kc) ^ swm) << 4);                \
        asm volatile("cp.async.cg.shared.global [%0], [%1], 16;" :: "r"(_da), "l"(_sa)); \
        asm volatile("cp.async.cg.shared.global [%0], [%1], 16;" :: "r"(_db), "l"(_sb)); \
    }                                                                           \
    asm volatile("cp.async.commit_group;");                                     \
} while (0)

    ISSUE(0, 0);
    ISSUE(1, 1);
    ISSUE(2, 2);
    ISSUE(3, 3);

    // in-block tqkv overlaps with prefetch latency
    {
        int outi = tid >> 1, half = tid & 1;
        int fr = outi >> 6, hd = outi & 63;
        const float4* tp = (const float4*)(te + (size_t)(bb * 16 + l0 + fr) * D_) + half * 64;
        const float4* wp = (const float4*)(Wt + (size_t)(third * 64 + hd) * D_) + half * 64;
        float acc = 0.f;
#pragma unroll 8
        for (int k = 0; k < 64; k++) {
            float4 a = tp[k], w = wp[k];
            acc += a.x * w.x + a.y * w.y + a.z * w.z + a.w * w.w;
        }
        acc += __shfl_xor_sync(0xffffffffu, acc, 1);
        if (!half) s_tq[outi] = acc;
    }

    int lane = tid & 31, warp = tid >> 5;
    int wm = warp & 1, wn = warp >> 1;
    uint32_t aAddr[4]; int aXor[4];
    int rA = lane & 15, kcbA = lane >> 4;
#pragma unroll
    for (int im = 0; im < 4; im++) {
        int mr = wm * 64 + im * 16 + rA;
        aAddr[im] = aBase + mr * 64;
        aXor[im] = (mr >> 1) & 3;
    }
    uint32_t bAddr[2]; int bXor[2];
    int kcbB = (lane >> 3) & 1;
#pragma unroll
    for (int p = 0; p < 2; p++) {
        int nr = wn * 32 + p * 16 + (lane & 7) + ((lane >> 4) << 3);
        bAddr[p] = bBase + nr * 64;
        bXor[p] = (nr >> 1) & 3;
    }

    float c[4][4][4] = {};

    for (int it = 0; it < 24; it++) {
        if (it < 23) {
            asm volatile("cp.async.wait_group 2;" ::: "memory");
        } else {
            asm volatile("cp.async.wait_group 0;" ::: "memory");
        }
        __syncthreads();
        int k0 = 2 * it;
        if (k0 + 4 < 48) ISSUE(k0 + 4, (k0 + 4) % 6);
        if (k0 + 5 < 48) ISSUE(k0 + 5, (k0 + 5) % 6);
#pragma unroll
        for (int half = 0; half < 2; half++) {
            int cur = (k0 + half) % 6;
#pragma unroll
            for (int s = 0; s < 2; s++) {
                uint32_t a[4][4];
#pragma unroll
                for (int im = 0; im < 4; im++)
                    ldsm4(a[im], aAddr[im] + cur * 8192 + (((kcbA + 2 * s) ^ aXor[im]) << 4));
                uint32_t bq[2][4];
#pragma unroll
                for (int p = 0; p < 2; p++)
                    ldsm4(bq[p], bAddr[p] + cur * 8192 + (((kcbB + 2 * s) ^ bXor[p]) << 4));
#pragma unroll
                for (int im = 0; im < 4; im++)
#pragma unroll
                    for (int in = 0; in < 4; in++)
                        mma16816(c[im][in], a[im], bq[in >> 1][(in & 1) * 2], bq[in >> 1][(in & 1) * 2 + 1]);
            }
        }
    }

    // ---- NEW epilogue: stage through smem, coalesced global stores ----
    __syncthreads();   // main-loop smem reads done; pipeline region reusable
    const float inv_scale = 0.044194173824159216f;  // 1/sqrt(512)
    int gid = lane >> 2, tig = lane & 3;

    if (third == 0) {
        float* stage = (float*)smem_raw;   // [128][132] fp32, 67.6KB
#pragma unroll
        for (int im = 0; im < 4; im++) {
#pragma unroll
            for (int hrow = 0; hrow < 2; hrow++) {
                int row = wm * 64 + im * 16 + gid + hrow * 8;
                int frl = ((m0 + row) >> 6) & 1;
#pragma unroll
                for (int in = 0; in < 4; in++) {
                    int col = wn * 32 + in * 8 + 2 * tig;
                    int hd = col & 63;
                    float v0 = (c[im][in][2 * hrow + 0] + s_tq[frl * 64 + hd]) * inv_scale;
                    float v1 = (c[im][in][2 * hrow + 1] + s_tq[frl * 64 + hd + 1]) * inv_scale;
                    stage[row * 132 + col]     = v0;
                    stage[row * 132 + col + 1] = v1;
                }
            }
        }
        __syncthreads();
        for (int cc = tid; cc < 4096; cc += 256) {
            int row = cc >> 5, ch = cc & 31;
            float4 v = *(const float4*)(stage + row * 132 + ch * 4);
            int col = ch * 4;
            int e = e0 + col;
            int h = (e >> 6) & 7, hd = col & 63;
            int grow = m0 + row;
            int b = grow >> 10, l = (grow >> 6) & 15, nt = grow & 63;
            *(float4*)(g_Q + (size_t)((b * H_ + h) * NTOK_ + l * 64 + nt) * HD_ + hd) = v;
        }
    } else {
        uint8_t* stH = (uint8_t*)smem_raw;        // [128][272B] hi plane (256B data + pad)
        uint8_t* stL = stH + 128 * 272;           // lo plane; total 69.6KB
#pragma unroll
        for (int im = 0; im < 4; im++) {
#pragma unroll
            for (int hrow = 0; hrow < 2; hrow++) {
                int row = wm * 64 + im * 16 + gid + hrow * 8;
                int frl = ((m0 + row) >> 6) & 1;
#pragma unroll
                for (int in = 0; in < 4; in++) {
                    int col = wn * 32 + in * 8 + 2 * tig;
                    int hd = col & 63;
                    float v0 = c[im][in][2 * hrow + 0] + s_tq[frl * 64 + hd];
                    float v1 = c[im][in][2 * hrow + 1] + s_tq[frl * 64 + hd + 1];
                    __nv_bfloat16 h0 = __float2bfloat16_rn(v0), h1 = __float2bfloat16_rn(v1);
                    __nv_bfloat162 hv = __halves2bfloat162(h0, h1);
                    __nv_bfloat162 lv = __floats2bfloat162_rn(v0 - __bfloat162float(h0),
                                                              v1 - __bfloat162float(h1));
                    *(uint32_t*)(stH + row * 272 + col * 2) = *(uint32_t*)&hv;
                    *(uint32_t*)(stL + row * 272 + col * 2) = *(uint32_t*)&lv;
                }
            }
        }
        __syncthreads();
        __nv_bfloat16* hiA = (third == 1) ? g_Khi : g_Vhi;
        __nv_bfloat16* loA = (third == 1) ? g_Klo : g_Vlo;
        for (int cc = tid; cc < 2048; cc += 256) {
            int row = cc >> 4, ch = cc & 15;
            int col = ch * 8;
            int e = e0 + col;
            int h = (e >> 6) & 7, hd = col & 63;
            int grow = m0 + row;
            int b = grow >> 10, l = (grow >> 6) & 15, nt = grow & 63;
            size_t off = (size_t)((b * H_ + h) * NTOK_ + l * 64 + nt) * HD_ + hd;
            *(uint4*)(hiA + off) = *(const uint4*)(stH + row * 272 + ch * 16);
            *(uint4*)(loA + off) = *(const uint4*)(stL + row * 272 + ch * 16);
        }
    }
}

// ---------------------------------------------------------------------------
// Kernel 2: tensor-core fused attention (r7 body + coalesced staged output)
// ---------------------------------------------------------------------------
#define ATT_KV     0
#define ATT_QS     0
#define ATT_ET     17408
#define ATT_QHI    65536
#define ATT_QLO    (ATT_QHI + 8192)
#define ATT_BIAS   (ATT_QLO + 8192)
#define ATT_LIST   (ATT_BIAS + 64 * 17 * 4)
#define ATT_SMEM   (ATT_LIST + 68)

__global__ __launch_bounds__(128, 2) void attn_kernel(const int* __restrict__ pos,
                                                      const int* __restrict__ mask,
                                                      const float* __restrict__ emb,
                                                      float* __restrict__ out) {
    uint32_t sbase = smem_u32(smem_raw);
    float (*Qs)[68] = (float(*)[68])(smem_raw + ATT_QS);
    float (*Et)[68] = (float(*)[68])(smem_raw + ATT_ET);
    float (*bias)[17] = (float(*)[17])(smem_raw + ATT_BIAS);
    int* list = (int*)(smem_raw + ATT_LIST);

    int ql = (L_ - 1) - blockIdx.x;
    int h = blockIdx.y, b = blockIdx.z;
    int tid = threadIdx.x;
    int lane = tid & 31, w = tid >> 5;
    int r0 = w * 16;
    int bh = b * H_ + h;

    if (tid == 0) {
        int nvl = 0;
        const int* mrow = mask + (b * L_ + ql) * L_;
#pragma unroll
        for (int kl = 0; kl < L_; kl++)
            if (mrow[kl] != 0) list[nvl++] = kl;
        list[16] = nvl;
    }

    const float* Qg = g_Q + ((size_t)bh * NTOK_ + ql * 64) * HD_;
    for (int i = tid; i < 1024; i += 128) {
        int r = i >> 4, c = (i & 15) << 2;
        *(float4*)&Qs[r][c] = *(const float4*)(Qg + r * HD_ + c);
    }
    for (int i = tid; i < 1024; i += 128) {
        int kl = i >> 6, c = i & 63;
        int p = pos[(b * L_ + ql) * L_ + kl];
        p = min(max(p, -8), 8) + 8;
        Et[kl][c] = emb[p * HD_ + c];
    }
    __syncthreads();
    int nv = list[16];

#pragma unroll
    for (int u = 0; u < 8; u++) {
        int id = tid + u * 128;
        int r = id >> 4, kl = id & 15;
        float acc = 0.f;
        const float* qrow = Qs[r];
        const float* erow = Et[kl];
#pragma unroll 16
        for (int c = 0; c < 64; c++) acc += qrow[c] * erow[c];
        bias[r][kl] = acc;
    }

#pragma unroll
    for (int i = 0; i < 4; i++) {
        int linear = i * 128 + tid;
        int row = linear >> 3, ch = linear & 7;
        const float* qp = &Qs[row][ch * 8];
        uint32_t hi4[4], lo4[4];
#pragma unroll
        for (int j = 0; j < 4; j++) {
            float x0 = qp[2 * j], x1 = qp[2 * j + 1];
            __nv_bfloat16 h0 = __float2bfloat16_rn(x0), h1 = __float2bfloat16_rn(x1);
            hi4[j] = packbf2(__bfloat162float(h0), __bfloat162float(h1));
            lo4[j] = packbf2(x0 - __bfloat162float(h0), x1 - __bfloat162float(h1));
        }
        uint32_t soff = row * 128 + ((ch ^ (row & 7)) << 4);
        *(uint4*)(smem_raw + ATT_QHI + soff) = *(uint4*)hi4;
        *(uint4*)(smem_raw + ATT_QLO + soff) = *(uint4*)lo4;
    }
    __syncthreads();

    uint32_t qh[4][4], qlr[4][4];
    {
        int lrow = (lane & 7) + 8 * ((lane >> 3) & 1);
        int khalf = lane >> 4;
#pragma unroll
        for (int kt = 0; kt < 4; kt++) {
            int qr = r0 + lrow;
            int qc = kt * 2 + khalf;
            uint32_t off = qr * 128 + ((qc ^ (qr & 7)) << 4);
            ldsm4(qh[kt],  sbase + ATT_QHI + off);
            ldsm4(qlr[kt], sbase + ATT_QLO + off);
        }
    }

    int g4 = lane >> 2;
    float m0r = -INFINITY, m1r = -INFINITY, l0r = 0.f, l1r = 0.f;
    float O[8][4] = {};

    int klrow = (lane & 7) + 8 * (lane >> 4);
    int kchalf = (lane >> 3) & 1;
    int vlrow = (lane & 7) + 8 * ((lane >> 3) & 1);
    int vchalf = lane >> 4;

    const __nv_bfloat16* tile_src[4] = {
        g_Khi + (size_t)bh * NTOK_ * HD_, g_Klo + (size_t)bh * NTOK_ * HD_,
        g_Vhi + (size_t)bh * NTOK_ * HD_, g_Vlo + (size_t)bh * NTOK_ * HD_
    };
    const __nv_bfloat16* mysrc = tile_src[w];
    uint32_t mydst = sbase + ATT_KV + w * 8192;

#define ISSUE_FRAME(f, stage) do {                                              \
    const __nv_bfloat16* _s = mysrc + (f) * 4096;                               \
    uint32_t _d = mydst + (stage) * 32768;                                      \
    _Pragma("unroll")                                                           \
    for (int _c = 0; _c < 16; _c++) {                                           \
        int _lin = _c * 32 + lane;                                              \
        int _row = _lin >> 3, _ch = _lin & 7;                                   \
        uint32_t _da = _d + _row * 128 + ((_ch ^ (_row & 7)) << 4);             \
        asm volatile("cp.async.cg.shared.global [%0], [%1], 16;"                \
                     :: "r"(_da), "l"(_s + _row * 64 + _ch * 8));               \
    }                                                                           \
    asm volatile("cp.async.commit_group;");                                     \
} while (0)

    ISSUE_FRAME(list[0], 0);

    for (int j = 0; j < nv; j++) {
        int stage = j & 1;
        if (j + 1 < nv) {
            ISSUE_FRAME(list[j + 1], (j + 1) & 1);
            asm volatile("cp.async.wait_group 1;" ::: "memory");
        } else {
            asm volatile("cp.async.wait_group 0;" ::: "memory");
        }
        __syncthreads();
        int kl = list[j];
        uint32_t khiB = sbase + ATT_KV + stage * 32768;
        uint32_t kloB = khiB + 8192;
        uint32_t vhiB = khiB + 16384;
        uint32_t vloB = khiB + 24576;

        float S[8][4];
        float bb0 = bias[r0 + g4][kl], bb1 = bias[r0 + 8 + g4][kl];
#pragma unroll
        for (int nt = 0; nt < 8; nt++) {
            S[nt][0] = bb0; S[nt][1] = bb0; S[nt][2] = bb1; S[nt][3] = bb1;
        }
#pragma unroll
        for (int kt = 0; kt < 4; kt++) {
#pragma unroll
            for (int np = 0; np < 4; np++) {
                int nr = np * 16 + klrow;
                int kc = kt * 2 + kchalf;
                uint32_t off = nr * 128 + ((kc ^ (nr & 7)) << 4);
                uint32_t kh[4], klo2[4];
                ldsm4(kh,   khiB + off);
                ldsm4(klo2, kloB + off);
                mma16816(S[2 * np],     qh[kt],  kh[0],   kh[1]);
                mma16816(S[2 * np + 1], qh[kt],  kh[2],   kh[3]);
                mma16816(S[2 * np],     qlr[kt], kh[0],   kh[1]);
                mma16816(S[2 * np + 1], qlr[kt], kh[2],   kh[3]);
                mma16816(S[2 * np],     qh[kt],  klo2[0], klo2[1]);
                mma16816(S[2 * np + 1], qh[kt],  klo2[2], klo2[3]);
            }
        }

        float mx0 = -INFINITY, mx1 = -INFINITY;
#pragma unroll
        for (int nt = 0; nt < 8; nt++) {
            mx0 = fmaxf(mx0, fmaxf(S[nt][0], S[nt][1]));
            mx1 = fmaxf(mx1, fmaxf(S[nt][2], S[nt][3]));
        }
        mx0 = fmaxf(mx0, __shfl_xor_sync(0xffffffffu, mx0, 1));
        mx0 = fmaxf(mx0, __shfl_xor_sync(0xffffffffu, mx0, 2));
        mx1 = fmaxf(mx1, __shfl_xor_sync(0xffffffffu, mx1, 1));
        mx1 = fmaxf(mx1, __shfl_xor_sync(0xffffffffu, mx1, 2));
        float mn0 = fmaxf(m0r, mx0), mn1 = fmaxf(m1r, mx1);
        float corr0 = __expf(m0r - mn0), corr1 = __expf(m1r - mn1);
        float sum0 = 0.f, sum1 = 0.f;
#pragma unroll
        for (int nt = 0; nt < 8; nt++) {
            S[nt][0] = __expf(S[nt][0] - mn0); S[nt][1] = __expf(S[nt][1] - mn0);
            S[nt][2] = __expf(S[nt][2] - mn1); S[nt][3] = __expf(S[nt][3] - mn1);
            sum0 += S[nt][0] + S[nt][1];
            sum1 += S[nt][2] + S[nt][3];
        }
        sum0 += __shfl_xor_sync(0xffffffffu, sum0, 1);
        sum0 += __shfl_xor_sync(0xffffffffu, sum0, 2);
        sum1 += __shfl_xor_sync(0xffffffffu, sum1, 1);
        sum1 += __shfl_xor_sync(0xffffffffu, sum1, 2);
        l0r = l0r * corr0 + sum0; m0r = mn0;
        l1r = l1r * corr1 + sum1; m1r = mn1;

        uint32_t ph[4][4], pl[4][4];
#pragma unroll
        for (int kt = 0; kt < 4; kt++) {
#pragma unroll
            for (int q = 0; q < 4; q++) {
                int nt = 2 * kt + (q >> 1);
                float x0 = S[nt][(q & 1) * 2], x1 = S[nt][(q & 1) * 2 + 1];
                __nv_bfloat16 hx0 = __float2bfloat16_rn(x0), hx1 = __float2bfloat16_rn(x1);
                __nv_bfloat162 hp2 = __halves2bfloat162(hx0, hx1);
                ph[kt][q] = *(uint32_t*)&hp2;
                __nv_bfloat162 lp2 = __floats2bfloat162_rn(x0 - __bfloat162float(hx0),
                                                           x1 - __bfloat162float(hx1));
                pl[kt][q] = *(uint32_t*)&lp2;
            }
        }

#pragma unroll
        for (int nt = 0; nt < 8; nt++) {
            O[nt][0] *= corr0; O[nt][1] *= corr0; O[nt][2] *= corr1; O[nt][3] *= corr1;
        }
#pragma unroll
        for (int kt = 0; kt < 4; kt++) {
#pragma unroll
            for (int np = 0; np < 4; np++) {
                int vr = kt * 16 + vlrow;
                int vc = np * 2 + vchalf;
                uint32_t off = vr * 128 + ((vc ^ (vr & 7)) << 4);
                uint32_t vh[4], vl[4];
                ldsm4t(vh, vhiB + off);
                ldsm4t(vl, vloB + off);
                mma16816(O[2 * np],     ph[kt], vh[0], vh[1]);
                mma16816(O[2 * np + 1], ph[kt], vh[2], vh[3]);
                mma16816(O[2 * np],     pl[kt], vh[0], vh[1]);
                mma16816(O[2 * np + 1], pl[kt], vh[2], vh[3]);
                mma16816(O[2 * np],     ph[kt], vl[0], vl[1]);
                mma16816(O[2 * np + 1], ph[kt], vl[2], vl[3]);
            }
        }
        __syncthreads();
    }

    // ---- NEW: stage normalized O in freed KV smem, coalesced store ----
    {
        float inv0 = 1.f / l0r, inv1 = 1.f / l1r;
        float* stage = (float*)smem_raw;   // [64][68] fp32 (KV region is free)
        int cl = 2 * (lane & 3);
#pragma unroll
        for (int nt = 0; nt < 8; nt++) {
            stage[(r0 + g4) * 68 + nt * 8 + cl]         = O[nt][0] * inv0;
            stage[(r0 + g4) * 68 + nt * 8 + cl + 1]     = O[nt][1] * inv0;
            stage[(r0 + 8 + g4) * 68 + nt * 8 + cl]     = O[nt][2] * inv1;
            stage[(r0 + 8 + g4) * 68 + nt * 8 + cl + 1] = O[nt][3] * inv1;
        }
        __syncthreads();
        for (int cc = tid; cc < 1024; cc += 128) {
            int row = cc >> 4, ch = cc & 15;
            float4 v = *(const float4*)(stage + row * 68 + ch * 4);
            *(float4*)(out + (size_t)((b * L_ + ql) * 64 + row) * D_ + h * HD_ + ch * 4) = v;
        }
    }
}

// ---------------------------------------------------------------------------
extern "C" void kernel_launch(void* const* d_in, const int* in_sizes, int n_in,
                              void* d_out, int out_size) {
    const float* x    = (const float*)d_in[0];
    const float* te   = (const float*)d_in[1];
    const int*   pos  = (const int*)d_in[2];
    const int*   mask = (const int*)d_in[3];
    const float* Wqkv = (const float*)d_in[4];
    const float* Wt   = (const float*)d_in[5];
    const float* emb  = (const float*)d_in[6];
    float* out = (float*)d_out;

    cudaFuncSetAttribute(qkv_gemm, cudaFuncAttributeMaxDynamicSharedMemorySize, GEMM_SMEM);
    cudaFuncSetAttribute(attn_kernel, cudaFuncAttributeMaxDynamicSharedMemorySize, ATT_SMEM);

    split_kernel<<<(XQUADS + WQUADS) / 256, 256>>>(x, Wqkv);
    qkv_gemm<<<dim3(E3_ / 128, 4096 / 128), 256, GEMM_SMEM>>>(te, Wt);
    attn_kernel<<<dim3(L_, H_, B_), 128, ATT_SMEM>>>(pos, mask, emb, out);
}

// round 11
// speedup vs baseline: 1.4975x; 1.1354x over previous
#include <cuda_runtime.h>
#include <cuda_bf16.h>
#include <cuda_fp16.h>
#include <math.h>
#include <stdint.h>

#define B_    4
#define L_    16
#define D_    512
#define H_    8
#define HD_   64
#define NTOK_ 1024
#define E3_   1536

// Scratch (allocation-free rule: __device__ globals)
__device__ float g_Q[B_ * H_ * NTOK_ * HD_];
__device__ __nv_bfloat16 g_Khi[B_ * H_ * NTOK_ * HD_];
__device__ __nv_bfloat16 g_Klo[B_ * H_ * NTOK_ * HD_];
__device__ __nv_bfloat16 g_Vhi[B_ * H_ * NTOK_ * HD_];
__device__ __nv_bfloat16 g_Vlo[B_ * H_ * NTOK_ * HD_];
__device__ __half g_Xhi[4096 * 512];
__device__ __half g_Xlo[4096 * 512];
__device__ __half g_Whi[1536 * 512];

__device__ __forceinline__ uint32_t smem_u32(const void* p) {
    uint32_t a;
    asm("{ .reg .u64 t; cvta.to.shared.u64 t, %1; cvt.u32.u64 %0, t; }" : "=r"(a) : "l"(p));
    return a;
}
__device__ __forceinline__ void ldsm4(uint32_t* r, uint32_t addr) {
    asm volatile("ldmatrix.sync.aligned.m8n8.x4.shared.b16 {%0,%1,%2,%3}, [%4];"
        : "=r"(r[0]), "=r"(r[1]), "=r"(r[2]), "=r"(r[3]) : "r"(addr));
}
__device__ __forceinline__ void ldsm4t(uint32_t* r, uint32_t addr) {
    asm volatile("ldmatrix.sync.aligned.m8n8.x4.trans.shared.b16 {%0,%1,%2,%3}, [%4];"
        : "=r"(r[0]), "=r"(r[1]), "=r"(r[2]), "=r"(r[3]) : "r"(addr));
}
// bf16 mma (attention)
__device__ __forceinline__ void mma16816(float* c, const uint32_t* a, uint32_t b0, uint32_t b1) {
    asm volatile("mma.sync.aligned.m16n8k16.row.col.f32.bf16.bf16.f32 "
        "{%0,%1,%2,%3}, {%4,%5,%6,%7}, {%8,%9}, {%0,%1,%2,%3};"
        : "+f"(c[0]), "+f"(c[1]), "+f"(c[2]), "+f"(c[3])
        : "r"(a[0]), "r"(a[1]), "r"(a[2]), "r"(a[3]), "r"(b0), "r"(b1));
}
// fp16 mma (QKV GEMM)
__device__ __forceinline__ void mma16816h(float* c, const uint32_t* a, uint32_t b0, uint32_t b1) {
    asm volatile("mma.sync.aligned.m16n8k16.row.col.f32.f16.f16.f32 "
        "{%0,%1,%2,%3}, {%4,%5,%6,%7}, {%8,%9}, {%0,%1,%2,%3};"
        : "+f"(c[0]), "+f"(c[1]), "+f"(c[2]), "+f"(c[3])
        : "r"(a[0]), "r"(a[1]), "r"(a[2]), "r"(a[3]), "r"(b0), "r"(b1));
}
__device__ __forceinline__ uint32_t packbf2(float a, float b) {
    __nv_bfloat162 t = __floats2bfloat162_rn(a, b);
    return *reinterpret_cast<uint32_t*>(&t);
}

extern __shared__ char smem_raw[];

// ---------------------------------------------------------------------------
// Kernel 0: split X into fp16 (hi, lo); W into fp16 hi only (2-term scheme).
// ---------------------------------------------------------------------------
#define XQUADS 524288   // 4096*512/4
#define WQUADS 196608   // 1536*512/4

__global__ __launch_bounds__(256) void split_kernel(const float* __restrict__ x,
                                                    const float* __restrict__ W) {
    int i = blockIdx.x * 256 + threadIdx.x;
    if (i < XQUADS) {
        float4 v = ((const float4*)x)[i];
        float f[4] = {v.x, v.y, v.z, v.w};
        __half2* hp = (__half2*)g_Xhi;
        __half2* lp = (__half2*)g_Xlo;
#pragma unroll
        for (int j = 0; j < 2; j++) {
            __half h0 = __float2half_rn(f[2 * j]);
            __half h1 = __float2half_rn(f[2 * j + 1]);
            __half l0 = __float2half_rn(f[2 * j] - __half2float(h0));
            __half l1 = __float2half_rn(f[2 * j + 1] - __half2float(h1));
            hp[i * 2 + j] = __halves2half2(h0, h1);
            lp[i * 2 + j] = __halves2half2(l0, l1);
        }
    } else {
        int idx = i - XQUADS;
        float4 v = ((const float4*)W)[idx];
        float f[4] = {v.x, v.y, v.z, v.w};
        __half2* hp = (__half2*)g_Whi;
#pragma unroll
        for (int j = 0; j < 2; j++) {
            __half h0 = __float2half_rn(f[2 * j]);
            __half h1 = __float2half_rn(f[2 * j + 1]);
            hp[idx * 2 + j] = __halves2half2(h0, h1);
        }
    }
}

// ---------------------------------------------------------------------------
// Kernel 1: QKV GEMM via fp16 mma.sync, 2-term split: K' = 1024.
// C = [Xhi|Xlo] . [Whi|Whi]^T  (dropped hi.lo term ~2^-11)
// r9 mainloop structure (6-stage ring, 2 chunks/barrier), 16 iterations.
// Coalesced smem-staged epilogue; K/V emitted as bf16 hi/lo for attn.
// ---------------------------------------------------------------------------
#define GEMM_SMEM (12 * 8192 + 512)

__global__ __launch_bounds__(256, 2) void qkv_gemm(const float* __restrict__ te,
                                                   const float* __restrict__ Wt) {
    uint32_t aBase = smem_u32(smem_raw);
    uint32_t bBase = aBase + 6 * 8192;
    float* s_tq = (float*)(smem_raw + 12 * 8192);

    int tid = threadIdx.x;
    int m0 = blockIdx.y * 128, e0 = blockIdx.x * 128;
    int bb = m0 >> 10, l0 = (m0 >> 6) & 15, third = e0 >> 9;

    int mld = tid >> 1;
    int kc0 = (tid & 1) * 2;
    int swm = (mld >> 1) & 3;
    uint32_t dA0 = aBase + mld * 64, dB0 = bBase + mld * 64;
    const __half* Asrc = g_Xhi + (size_t)(m0 + mld) * 512;
    const __half* Alo  = g_Xlo + (size_t)(m0 + mld) * 512;
    const __half* Bsrc = g_Whi + (size_t)(e0 + mld) * 512;

#define ISSUE(ki, st) do {                                                      \
    int _r = (ki) >> 4, _kb = ((ki) & 15) * 32;                                 \
    const __half* _ap = (_r == 1) ? Alo : Asrc;                                 \
    _Pragma("unroll")                                                           \
    for (int _j = 0; _j < 2; _j++) {                                            \
        int _kc = kc0 + _j;                                                     \
        const void* _sa = _ap + _kb + _kc * 8;                                  \
        const void* _sb = Bsrc + _kb + _kc * 8;                                 \
        uint32_t _da = dA0 + (st) * 8192 + (((_kc) ^ swm) << 4);                \
        uint32_t _db = dB0 + (st) * 8192 + (((_kc) ^ swm) << 4);                \
        asm volatile("cp.async.cg.shared.global [%0], [%1], 16;" :: "r"(_da), "l"(_sa)); \
        asm volatile("cp.async.cg.shared.global [%0], [%1], 16;" :: "r"(_db), "l"(_sb)); \
    }                                                                           \
    asm volatile("cp.async.commit_group;");                                     \
} while (0)

    ISSUE(0, 0);
    ISSUE(1, 1);
    ISSUE(2, 2);
    ISSUE(3, 3);

    // in-block tqkv overlaps with prefetch latency (fp32, unchanged)
    {
        int outi = tid >> 1, half = tid & 1;
        int fr = outi >> 6, hd = outi & 63;
        const float4* tp = (const float4*)(te + (size_t)(bb * 16 + l0 + fr) * D_) + half * 64;
        const float4* wp = (const float4*)(Wt + (size_t)(third * 64 + hd) * D_) + half * 64;
        float acc = 0.f;
#pragma unroll 8
        for (int k = 0; k < 64; k++) {
            float4 a = tp[k], w = wp[k];
            acc += a.x * w.x + a.y * w.y + a.z * w.z + a.w * w.w;
        }
        acc += __shfl_xor_sync(0xffffffffu, acc, 1);
        if (!half) s_tq[outi] = acc;
    }

    int lane = tid & 31, warp = tid >> 5;
    int wm = warp & 1, wn = warp >> 1;
    uint32_t aAddr[4]; int aXor[4];
    int rA = lane & 15, kcbA = lane >> 4;
#pragma unroll
    for (int im = 0; im < 4; im++) {
        int mr = wm * 64 + im * 16 + rA;
        aAddr[im] = aBase + mr * 64;
        aXor[im] = (mr >> 1) & 3;
    }
    uint32_t bAddr[2]; int bXor[2];
    int kcbB = (lane >> 3) & 1;
#pragma unroll
    for (int p = 0; p < 2; p++) {
        int nr = wn * 32 + p * 16 + (lane & 7) + ((lane >> 4) << 3);
        bAddr[p] = bBase + nr * 64;
        bXor[p] = (nr >> 1) & 3;
    }

    float c[4][4][4] = {};

    for (int it = 0; it < 16; it++) {
        if (it < 15) {
            asm volatile("cp.async.wait_group 2;" ::: "memory");
        } else {
            asm volatile("cp.async.wait_group 0;" ::: "memory");
        }
        __syncthreads();
        int k0 = 2 * it;
        if (k0 + 4 < 32) ISSUE(k0 + 4, (k0 + 4) % 6);
        if (k0 + 5 < 32) ISSUE(k0 + 5, (k0 + 5) % 6);
#pragma unroll
        for (int half = 0; half < 2; half++) {
            int cur = (k0 + half) % 6;
#pragma unroll
            for (int s = 0; s < 2; s++) {
                uint32_t a[4][4];
#pragma unroll
                for (int im = 0; im < 4; im++)
                    ldsm4(a[im], aAddr[im] + cur * 8192 + (((kcbA + 2 * s) ^ aXor[im]) << 4));
                uint32_t bq[2][4];
#pragma unroll
                for (int p = 0; p < 2; p++)
                    ldsm4(bq[p], bAddr[p] + cur * 8192 + (((kcbB + 2 * s) ^ bXor[p]) << 4));
#pragma unroll
                for (int im = 0; im < 4; im++)
#pragma unroll
                    for (int in = 0; in < 4; in++)
                        mma16816h(c[im][in], a[im], bq[in >> 1][(in & 1) * 2], bq[in >> 1][(in & 1) * 2 + 1]);
            }
        }
    }

    // ---- coalesced smem-staged epilogue (same as r10) ----
    __syncthreads();
    const float inv_scale = 0.044194173824159216f;  // 1/sqrt(512)
    int gid = lane >> 2, tig = lane & 3;

    if (third == 0) {
        float* stage = (float*)smem_raw;   // [128][132] fp32
#pragma unroll
        for (int im = 0; im < 4; im++) {
#pragma unroll
            for (int hrow = 0; hrow < 2; hrow++) {
                int row = wm * 64 + im * 16 + gid + hrow * 8;
                int frl = ((m0 + row) >> 6) & 1;
#pragma unroll
                for (int in = 0; in < 4; in++) {
                    int col = wn * 32 + in * 8 + 2 * tig;
                    int hd = col & 63;
                    float v0 = (c[im][in][2 * hrow + 0] + s_tq[frl * 64 + hd]) * inv_scale;
                    float v1 = (c[im][in][2 * hrow + 1] + s_tq[frl * 64 + hd + 1]) * inv_scale;
                    stage[row * 132 + col]     = v0;
                    stage[row * 132 + col + 1] = v1;
                }
            }
        }
        __syncthreads();
        for (int cc = tid; cc < 4096; cc += 256) {
            int row = cc >> 5, ch = cc & 31;
            float4 v = *(const float4*)(stage + row * 132 + ch * 4);
            int col = ch * 4;
            int e = e0 + col;
            int h = (e >> 6) & 7, hd = col & 63;
            int grow = m0 + row;
            int b = grow >> 10, l = (grow >> 6) & 15, nt = grow & 63;
            *(float4*)(g_Q + (size_t)((b * H_ + h) * NTOK_ + l * 64 + nt) * HD_ + hd) = v;
        }
    } else {
        uint8_t* stH = (uint8_t*)smem_raw;
        uint8_t* stL = stH + 128 * 272;
#pragma unroll
        for (int im = 0; im < 4; im++) {
#pragma unroll
            for (int hrow = 0; hrow < 2; hrow++) {
                int row = wm * 64 + im * 16 + gid + hrow * 8;
                int frl = ((m0 + row) >> 6) & 1;
#pragma unroll
                for (int in = 0; in < 4; in++) {
                    int col = wn * 32 + in * 8 + 2 * tig;
                    int hd = col & 63;
                    float v0 = c[im][in][2 * hrow + 0] + s_tq[frl * 64 + hd];
                    float v1 = c[im][in][2 * hrow + 1] + s_tq[frl * 64 + hd + 1];
                    __nv_bfloat16 h0 = __float2bfloat16_rn(v0), h1 = __float2bfloat16_rn(v1);
                    __nv_bfloat162 hv = __halves2bfloat162(h0, h1);
                    __nv_bfloat162 lv = __floats2bfloat162_rn(v0 - __bfloat162float(h0),
                                                              v1 - __bfloat162float(h1));
                    *(uint32_t*)(stH + row * 272 + col * 2) = *(uint32_t*)&hv;
                    *(uint32_t*)(stL + row * 272 + col * 2) = *(uint32_t*)&lv;
                }
            }
        }
        __syncthreads();
        __nv_bfloat16* hiA = (third == 1) ? g_Khi : g_Vhi;
        __nv_bfloat16* loA = (third == 1) ? g_Klo : g_Vlo;
        for (int cc = tid; cc < 2048; cc += 256) {
            int row = cc >> 4, ch = cc & 15;
            int col = ch * 8;
            int e = e0 + col;
            int h = (e >> 6) & 7, hd = col & 63;
            int grow = m0 + row;
            int b = grow >> 10, l = (grow >> 6) & 15, nt = grow & 63;
            size_t off = (size_t)((b * H_ + h) * NTOK_ + l * 64 + nt) * HD_ + hd;
            *(uint4*)(hiA + off) = *(const uint4*)(stH + row * 272 + ch * 16);
            *(uint4*)(loA + off) = *(const uint4*)(stL + row * 272 + ch * 16);
        }
    }
}

// ---------------------------------------------------------------------------
// Kernel 2: tensor-core fused attention (r10 exact — unchanged)
// ---------------------------------------------------------------------------
#define ATT_KV     0
#define ATT_QS     0
#define ATT_ET     17408
#define ATT_QHI    65536
#define ATT_QLO    (ATT_QHI + 8192)
#define ATT_BIAS   (ATT_QLO + 8192)
#define ATT_LIST   (ATT_BIAS + 64 * 17 * 4)
#define ATT_SMEM   (ATT_LIST + 68)

__global__ __launch_bounds__(128, 2) void attn_kernel(const int* __restrict__ pos,
                                                      const int* __restrict__ mask,
                                                      const float* __restrict__ emb,
                                                      float* __restrict__ out) {
    uint32_t sbase = smem_u32(smem_raw);
    float (*Qs)[68] = (float(*)[68])(smem_raw + ATT_QS);
    float (*Et)[68] = (float(*)[68])(smem_raw + ATT_ET);
    float (*bias)[17] = (float(*)[17])(smem_raw + ATT_BIAS);
    int* list = (int*)(smem_raw + ATT_LIST);

    int ql = (L_ - 1) - blockIdx.x;
    int h = blockIdx.y, b = blockIdx.z;
    int tid = threadIdx.x;
    int lane = tid & 31, w = tid >> 5;
    int r0 = w * 16;
    int bh = b * H_ + h;

    if (tid == 0) {
        int nvl = 0;
        const int* mrow = mask + (b * L_ + ql) * L_;
#pragma unroll
        for (int kl = 0; kl < L_; kl++)
            if (mrow[kl] != 0) list[nvl++] = kl;
        list[16] = nvl;
    }

    const float* Qg = g_Q + ((size_t)bh * NTOK_ + ql * 64) * HD_;
    for (int i = tid; i < 1024; i += 128) {
        int r = i >> 4, c = (i & 15) << 2;
        *(float4*)&Qs[r][c] = *(const float4*)(Qg + r * HD_ + c);
    }
    for (int i = tid; i < 1024; i += 128) {
        int kl = i >> 6, c = i & 63;
        int p = pos[(b * L_ + ql) * L_ + kl];
        p = min(max(p, -8), 8) + 8;
        Et[kl][c] = emb[p * HD_ + c];
    }
    __syncthreads();
    int nv = list[16];

#pragma unroll
    for (int u = 0; u < 8; u++) {
        int id = tid + u * 128;
        int r = id >> 4, kl = id & 15;
        float acc = 0.f;
        const float* qrow = Qs[r];
        const float* erow = Et[kl];
#pragma unroll 16
        for (int c = 0; c < 64; c++) acc += qrow[c] * erow[c];
        bias[r][kl] = acc;
    }

#pragma unroll
    for (int i = 0; i < 4; i++) {
        int linear = i * 128 + tid;
        int row = linear >> 3, ch = linear & 7;
        const float* qp = &Qs[row][ch * 8];
        uint32_t hi4[4], lo4[4];
#pragma unroll
        for (int j = 0; j < 4; j++) {
            float x0 = qp[2 * j], x1 = qp[2 * j + 1];
            __nv_bfloat16 h0 = __float2bfloat16_rn(x0), h1 = __float2bfloat16_rn(x1);
            hi4[j] = packbf2(__bfloat162float(h0), __bfloat162float(h1));
            lo4[j] = packbf2(x0 - __bfloat162float(h0), x1 - __bfloat162float(h1));
        }
        uint32_t soff = row * 128 + ((ch ^ (row & 7)) << 4);
        *(uint4*)(smem_raw + ATT_QHI + soff) = *(uint4*)hi4;
        *(uint4*)(smem_raw + ATT_QLO + soff) = *(uint4*)lo4;
    }
    __syncthreads();

    uint32_t qh[4][4], qlr[4][4];
    {
        int lrow = (lane & 7) + 8 * ((lane >> 3) & 1);
        int khalf = lane >> 4;
#pragma unroll
        for (int kt = 0; kt < 4; kt++) {
            int qr = r0 + lrow;
            int qc = kt * 2 + khalf;
            uint32_t off = qr * 128 + ((qc ^ (qr & 7)) << 4);
            ldsm4(qh[kt],  sbase + ATT_QHI + off);
            ldsm4(qlr[kt], sbase + ATT_QLO + off);
        }
    }

    int g4 = lane >> 2;
    float m0r = -INFINITY, m1r = -INFINITY, l0r = 0.f, l1r = 0.f;
    float O[8][4] = {};

    int klrow = (lane & 7) + 8 * (lane >> 4);
    int kchalf = (lane >> 3) & 1;
    int vlrow = (lane & 7) + 8 * ((lane >> 3) & 1);
    int vchalf = lane >> 4;

    const __nv_bfloat16* tile_src[4] = {
        g_Khi + (size_t)bh * NTOK_ * HD_, g_Klo + (size_t)bh * NTOK_ * HD_,
        g_Vhi + (size_t)bh * NTOK_ * HD_, g_Vlo + (size_t)bh * NTOK_ * HD_
    };
    const __nv_bfloat16* mysrc = tile_src[w];
    uint32_t mydst = sbase + ATT_KV + w * 8192;

#define ISSUE_FRAME(f, stage) do {                                              \
    const __nv_bfloat16* _s = mysrc + (f) * 4096;                               \
    uint32_t _d = mydst + (stage) * 32768;                                      \
    _Pragma("unroll")                                                           \
    for (int _c = 0; _c < 16; _c++) {                                           \
        int _lin = _c * 32 + lane;                                              \
        int _row = _lin >> 3, _ch = _lin & 7;                                   \
        uint32_t _da = _d + _row * 128 + ((_ch ^ (_row & 7)) << 4);             \
        asm volatile("cp.async.cg.shared.global [%0], [%1], 16;"                \
                     :: "r"(_da), "l"(_s + _row * 64 + _ch * 8));               \
    }                                                                           \
    asm volatile("cp.async.commit_group;");                                     \
} while (0)

    ISSUE_FRAME(list[0], 0);

    for (int j = 0; j < nv; j++) {
        int stage = j & 1;
        if (j + 1 < nv) {
            ISSUE_FRAME(list[j + 1], (j + 1) & 1);
            asm volatile("cp.async.wait_group 1;" ::: "memory");
        } else {
            asm volatile("cp.async.wait_group 0;" ::: "memory");
        }
        __syncthreads();
        int kl = list[j];
        uint32_t khiB = sbase + ATT_KV + stage * 32768;
        uint32_t kloB = khiB + 8192;
        uint32_t vhiB = khiB + 16384;
        uint32_t vloB = khiB + 24576;

        float S[8][4];
        float bb0 = bias[r0 + g4][kl], bb1 = bias[r0 + 8 + g4][kl];
#pragma unroll
        for (int nt = 0; nt < 8; nt++) {
            S[nt][0] = bb0; S[nt][1] = bb0; S[nt][2] = bb1; S[nt][3] = bb1;
        }
#pragma unroll
        for (int kt = 0; kt < 4; kt++) {
#pragma unroll
            for (int np = 0; np < 4; np++) {
                int nr = np * 16 + klrow;
                int kc = kt * 2 + kchalf;
                uint32_t off = nr * 128 + ((kc ^ (nr & 7)) << 4);
                uint32_t kh[4], klo2[4];
                ldsm4(kh,   khiB + off);
                ldsm4(klo2, kloB + off);
                mma16816(S[2 * np],     qh[kt],  kh[0],   kh[1]);
                mma16816(S[2 * np + 1], qh[kt],  kh[2],   kh[3]);
                mma16816(S[2 * np],     qlr[kt], kh[0],   kh[1]);
                mma16816(S[2 * np + 1], qlr[kt], kh[2],   kh[3]);
                mma16816(S[2 * np],     qh[kt],  klo2[0], klo2[1]);
                mma16816(S[2 * np + 1], qh[kt],  klo2[2], klo2[3]);
            }
        }

        float mx0 = -INFINITY, mx1 = -INFINITY;
#pragma unroll
        for (int nt = 0; nt < 8; nt++) {
            mx0 = fmaxf(mx0, fmaxf(S[nt][0], S[nt][1]));
            mx1 = fmaxf(mx1, fmaxf(S[nt][2], S[nt][3]));
        }
        mx0 = fmaxf(mx0, __shfl_xor_sync(0xffffffffu, mx0, 1));
        mx0 = fmaxf(mx0, __shfl_xor_sync(0xffffffffu, mx0, 2));
        mx1 = fmaxf(mx1, __shfl_xor_sync(0xffffffffu, mx1, 1));
        mx1 = fmaxf(mx1, __shfl_xor_sync(0xffffffffu, mx1, 2));
        float mn0 = fmaxf(m0r, mx0), mn1 = fmaxf(m1r, mx1);
        float corr0 = __expf(m0r - mn0), corr1 = __expf(m1r - mn1);
        float sum0 = 0.f, sum1 = 0.f;
#pragma unroll
        for (int nt = 0; nt < 8; nt++) {
            S[nt][0] = __expf(S[nt][0] - mn0); S[nt][1] = __expf(S[nt][1] - mn0);
            S[nt][2] = __expf(S[nt][2] - mn1); S[nt][3] = __expf(S[nt][3] - mn1);
            sum0 += S[nt][0] + S[nt][1];
            sum1 += S[nt][2] + S[nt][3];
        }
        sum0 += __shfl_xor_sync(0xffffffffu, sum0, 1);
        sum0 += __shfl_xor_sync(0xffffffffu, sum0, 2);
        sum1 += __shfl_xor_sync(0xffffffffu, sum1, 1);
        sum1 += __shfl_xor_sync(0xffffffffu, sum1, 2);
        l0r = l0r * corr0 + sum0; m0r = mn0;
        l1r = l1r * corr1 + sum1; m1r = mn1;

        uint32_t ph[4][4], pl[4][4];
#pragma unroll
        for (int kt = 0; kt < 4; kt++) {
#pragma unroll
            for (int q = 0; q < 4; q++) {
                int nt = 2 * kt + (q >> 1);
                float x0 = S[nt][(q & 1) * 2], x1 = S[nt][(q & 1) * 2 + 1];
                __nv_bfloat16 hx0 = __float2bfloat16_rn(x0), hx1 = __float2bfloat16_rn(x1);
                __nv_bfloat162 hp2 = __halves2bfloat162(hx0, hx1);
                ph[kt][q] = *(uint32_t*)&hp2;
                __nv_bfloat162 lp2 = __floats2bfloat162_rn(x0 - __bfloat162float(hx0),
                                                           x1 - __bfloat162float(hx1));
                pl[kt][q] = *(uint32_t*)&lp2;
            }
        }

#pragma unroll
        for (int nt = 0; nt < 8; nt++) {
            O[nt][0] *= corr0; O[nt][1] *= corr0; O[nt][2] *= corr1; O[nt][3] *= corr1;
        }
#pragma unroll
        for (int kt = 0; kt < 4; kt++) {
#pragma unroll
            for (int np = 0; np < 4; np++) {
                int vr = kt * 16 + vlrow;
                int vc = np * 2 + vchalf;
                uint32_t off = vr * 128 + ((vc ^ (vr & 7)) << 4);
                uint32_t vh[4], vl[4];
                ldsm4t(vh, vhiB + off);
                ldsm4t(vl, vloB + off);
                mma16816(O[2 * np],     ph[kt], vh[0], vh[1]);
                mma16816(O[2 * np + 1], ph[kt], vh[2], vh[3]);
                mma16816(O[2 * np],     pl[kt], vh[0], vh[1]);
                mma16816(O[2 * np + 1], pl[kt], vh[2], vh[3]);
                mma16816(O[2 * np],     ph[kt], vl[0], vl[1]);
                mma16816(O[2 * np + 1], ph[kt], vl[2], vl[3]);
            }
        }
        __syncthreads();
    }

    {
        float inv0 = 1.f / l0r, inv1 = 1.f / l1r;
        float* stage = (float*)smem_raw;
        int cl = 2 * (lane & 3);
#pragma unroll
        for (int nt = 0; nt < 8; nt++) {
            stage[(r0 + g4) * 68 + nt * 8 + cl]         = O[nt][0] * inv0;
            stage[(r0 + g4) * 68 + nt * 8 + cl + 1]     = O[nt][1] * inv0;
            stage[(r0 + 8 + g4) * 68 + nt * 8 + cl]     = O[nt][2] * inv1;
            stage[(r0 + 8 + g4) * 68 + nt * 8 + cl + 1] = O[nt][3] * inv1;
        }
        __syncthreads();
        for (int cc = tid; cc < 1024; cc += 128) {
            int row = cc >> 4, ch = cc & 15;
            float4 v = *(const float4*)(stage + row * 68 + ch * 4);
            *(float4*)(out + (size_t)((b * L_ + ql) * 64 + row) * D_ + h * HD_ + ch * 4) = v;
        }
    }
}

// ---------------------------------------------------------------------------
extern "C" void kernel_launch(void* const* d_in, const int* in_sizes, int n_in,
                              void* d_out, int out_size) {
    const float* x    = (const float*)d_in[0];
    const float* te   = (const float*)d_in[1];
    const int*   pos  = (const int*)d_in[2];
    const int*   mask = (const int*)d_in[3];
    const float* Wqkv = (const float*)d_in[4];
    const float* Wt   = (const float*)d_in[5];
    const float* emb  = (const float*)d_in[6];
    float* out = (float*)d_out;

    cudaFuncSetAttribute(qkv_gemm, cudaFuncAttributeMaxDynamicSharedMemorySize, GEMM_SMEM);
    cudaFuncSetAttribute(attn_kernel, cudaFuncAttributeMaxDynamicSharedMemorySize, ATT_SMEM);

    split_kernel<<<(XQUADS + WQUADS) / 256, 256>>>(x, Wqkv);
    qkv_gemm<<<dim3(E3_ / 128, 4096 / 128), 256, GEMM_SMEM>>>(te, Wt);
    attn_kernel<<<dim3(L_, H_, B_), 128, ATT_SMEM>>>(pos, mask, emb, out);
}

// round 12
// speedup vs baseline: 1.6624x; 1.1101x over previous
#include <cuda_runtime.h>
#include <cuda_bf16.h>
#include <cuda_fp16.h>
#include <math.h>
#include <stdint.h>

#define B_    4
#define L_    16
#define D_    512
#define H_    8
#define HD_   64
#define NTOK_ 1024
#define E3_   1536

// Scratch (allocation-free rule: __device__ globals)
__device__ float g_Q[B_ * H_ * NTOK_ * HD_];
__device__ __half g_Khf[B_ * H_ * NTOK_ * HD_];
__device__ __half g_Vhf[B_ * H_ * NTOK_ * HD_];
__device__ __half g_Xhi[4096 * 512];
__device__ __half g_Xlo[4096 * 512];
__device__ __half g_Whi[1536 * 512];

__device__ __forceinline__ uint32_t smem_u32(const void* p) {
    uint32_t a;
    asm("{ .reg .u64 t; cvta.to.shared.u64 t, %1; cvt.u32.u64 %0, t; }" : "=r"(a) : "l"(p));
    return a;
}
__device__ __forceinline__ void ldsm4(uint32_t* r, uint32_t addr) {
    asm volatile("ldmatrix.sync.aligned.m8n8.x4.shared.b16 {%0,%1,%2,%3}, [%4];"
        : "=r"(r[0]), "=r"(r[1]), "=r"(r[2]), "=r"(r[3]) : "r"(addr));
}
__device__ __forceinline__ void ldsm4t(uint32_t* r, uint32_t addr) {
    asm volatile("ldmatrix.sync.aligned.m8n8.x4.trans.shared.b16 {%0,%1,%2,%3}, [%4];"
        : "=r"(r[0]), "=r"(r[1]), "=r"(r[2]), "=r"(r[3]) : "r"(addr));
}
__device__ __forceinline__ void mma16816h(float* c, const uint32_t* a, uint32_t b0, uint32_t b1) {
    asm volatile("mma.sync.aligned.m16n8k16.row.col.f32.f16.f16.f32 "
        "{%0,%1,%2,%3}, {%4,%5,%6,%7}, {%8,%9}, {%0,%1,%2,%3};"
        : "+f"(c[0]), "+f"(c[1]), "+f"(c[2]), "+f"(c[3])
        : "r"(a[0]), "r"(a[1]), "r"(a[2]), "r"(a[3]), "r"(b0), "r"(b1));
}
__device__ __forceinline__ uint32_t packh2(float a, float b) {
    __half2 t = __floats2half2_rn(a, b);
    return *reinterpret_cast<uint32_t*>(&t);
}

extern __shared__ char smem_raw[];

// ---------------------------------------------------------------------------
// Kernel 0: split X into fp16 (hi, lo); W into fp16 hi only (2-term scheme).
// ---------------------------------------------------------------------------
#define XQUADS 524288   // 4096*512/4
#define WQUADS 196608   // 1536*512/4

__global__ __launch_bounds__(256) void split_kernel(const float* __restrict__ x,
                                                    const float* __restrict__ W) {
    int i = blockIdx.x * 256 + threadIdx.x;
    if (i < XQUADS) {
        float4 v = ((const float4*)x)[i];
        float f[4] = {v.x, v.y, v.z, v.w};
        __half2* hp = (__half2*)g_Xhi;
        __half2* lp = (__half2*)g_Xlo;
#pragma unroll
        for (int j = 0; j < 2; j++) {
            __half h0 = __float2half_rn(f[2 * j]);
            __half h1 = __float2half_rn(f[2 * j + 1]);
            __half l0 = __float2half_rn(f[2 * j] - __half2float(h0));
            __half l1 = __float2half_rn(f[2 * j + 1] - __half2float(h1));
            hp[i * 2 + j] = __halves2half2(h0, h1);
            lp[i * 2 + j] = __halves2half2(l0, l1);
        }
    } else {
        int idx = i - XQUADS;
        float4 v = ((const float4*)W)[idx];
        float f[4] = {v.x, v.y, v.z, v.w};
        __half2* hp = (__half2*)g_Whi;
#pragma unroll
        for (int j = 0; j < 2; j++) {
            __half h0 = __float2half_rn(f[2 * j]);
            __half h1 = __float2half_rn(f[2 * j + 1]);
            hp[idx * 2 + j] = __halves2half2(h0, h1);
        }
    }
}

// ---------------------------------------------------------------------------
// Kernel 1: QKV GEMM via fp16 mma.sync, 2-term split: K' = 1024.
// Epilogue: Q -> fp32 (pre-scaled); K,V -> single-plane fp16.
// ---------------------------------------------------------------------------
#define GEMM_SMEM (12 * 8192 + 512)

__global__ __launch_bounds__(256, 2) void qkv_gemm(const float* __restrict__ te,
                                                   const float* __restrict__ Wt) {
    uint32_t aBase = smem_u32(smem_raw);
    uint32_t bBase = aBase + 6 * 8192;
    float* s_tq = (float*)(smem_raw + 12 * 8192);

    int tid = threadIdx.x;
    int m0 = blockIdx.y * 128, e0 = blockIdx.x * 128;
    int bb = m0 >> 10, l0 = (m0 >> 6) & 15, third = e0 >> 9;

    int mld = tid >> 1;
    int kc0 = (tid & 1) * 2;
    int swm = (mld >> 1) & 3;
    uint32_t dA0 = aBase + mld * 64, dB0 = bBase + mld * 64;
    const __half* Asrc = g_Xhi + (size_t)(m0 + mld) * 512;
    const __half* Alo  = g_Xlo + (size_t)(m0 + mld) * 512;
    const __half* Bsrc = g_Whi + (size_t)(e0 + mld) * 512;

#define ISSUE(ki, st) do {                                                      \
    int _r = (ki) >> 4, _kb = ((ki) & 15) * 32;                                 \
    const __half* _ap = (_r == 1) ? Alo : Asrc;                                 \
    _Pragma("unroll")                                                           \
    for (int _j = 0; _j < 2; _j++) {                                            \
        int _kc = kc0 + _j;                                                     \
        const void* _sa = _ap + _kb + _kc * 8;                                  \
        const void* _sb = Bsrc + _kb + _kc * 8;                                 \
        uint32_t _da = dA0 + (st) * 8192 + (((_kc) ^ swm) << 4);                \
        uint32_t _db = dB0 + (st) * 8192 + (((_kc) ^ swm) << 4);                \
        asm volatile("cp.async.cg.shared.global [%0], [%1], 16;" :: "r"(_da), "l"(_sa)); \
        asm volatile("cp.async.cg.shared.global [%0], [%1], 16;" :: "r"(_db), "l"(_sb)); \
    }                                                                           \
    asm volatile("cp.async.commit_group;");                                     \
} while (0)

    ISSUE(0, 0);
    ISSUE(1, 1);
    ISSUE(2, 2);
    ISSUE(3, 3);

    // in-block tqkv overlaps with prefetch latency (fp32)
    {
        int outi = tid >> 1, half = tid & 1;
        int fr = outi >> 6, hd = outi & 63;
        const float4* tp = (const float4*)(te + (size_t)(bb * 16 + l0 + fr) * D_) + half * 64;
        const float4* wp = (const float4*)(Wt + (size_t)(third * 64 + hd) * D_) + half * 64;
        float acc = 0.f;
#pragma unroll 8
        for (int k = 0; k < 64; k++) {
            float4 a = tp[k], w = wp[k];
            acc += a.x * w.x + a.y * w.y + a.z * w.z + a.w * w.w;
        }
        acc += __shfl_xor_sync(0xffffffffu, acc, 1);
        if (!half) s_tq[outi] = acc;
    }

    int lane = tid & 31, warp = tid >> 5;
    int wm = warp & 1, wn = warp >> 1;
    uint32_t aAddr[4]; int aXor[4];
    int rA = lane & 15, kcbA = lane >> 4;
#pragma unroll
    for (int im = 0; im < 4; im++) {
        int mr = wm * 64 + im * 16 + rA;
        aAddr[im] = aBase + mr * 64;
        aXor[im] = (mr >> 1) & 3;
    }
    uint32_t bAddr[2]; int bXor[2];
    int kcbB = (lane >> 3) & 1;
#pragma unroll
    for (int p = 0; p < 2; p++) {
        int nr = wn * 32 + p * 16 + (lane & 7) + ((lane >> 4) << 3);
        bAddr[p] = bBase + nr * 64;
        bXor[p] = (nr >> 1) & 3;
    }

    float c[4][4][4] = {};

    for (int it = 0; it < 16; it++) {
        if (it < 15) {
            asm volatile("cp.async.wait_group 2;" ::: "memory");
        } else {
            asm volatile("cp.async.wait_group 0;" ::: "memory");
        }
        __syncthreads();
        int k0 = 2 * it;
        if (k0 + 4 < 32) ISSUE(k0 + 4, (k0 + 4) % 6);
        if (k0 + 5 < 32) ISSUE(k0 + 5, (k0 + 5) % 6);
#pragma unroll
        for (int half = 0; half < 2; half++) {
            int cur = (k0 + half) % 6;
#pragma unroll
            for (int s = 0; s < 2; s++) {
                uint32_t a[4][4];
#pragma unroll
                for (int im = 0; im < 4; im++)
                    ldsm4(a[im], aAddr[im] + cur * 8192 + (((kcbA + 2 * s) ^ aXor[im]) << 4));
                uint32_t bq[2][4];
#pragma unroll
                for (int p = 0; p < 2; p++)
                    ldsm4(bq[p], bAddr[p] + cur * 8192 + (((kcbB + 2 * s) ^ bXor[p]) << 4));
#pragma unroll
                for (int im = 0; im < 4; im++)
#pragma unroll
                    for (int in = 0; in < 4; in++)
                        mma16816h(c[im][in], a[im], bq[in >> 1][(in & 1) * 2], bq[in >> 1][(in & 1) * 2 + 1]);
            }
        }
    }

    // ---- coalesced smem-staged epilogue ----
    __syncthreads();
    const float inv_scale = 0.044194173824159216f;  // 1/sqrt(512)
    int gid = lane >> 2, tig = lane & 3;

    if (third == 0) {
        float* stage = (float*)smem_raw;   // [128][132] fp32
#pragma unroll
        for (int im = 0; im < 4; im++) {
#pragma unroll
            for (int hrow = 0; hrow < 2; hrow++) {
                int row = wm * 64 + im * 16 + gid + hrow * 8;
                int frl = ((m0 + row) >> 6) & 1;
#pragma unroll
                for (int in = 0; in < 4; in++) {
                    int col = wn * 32 + in * 8 + 2 * tig;
                    int hd = col & 63;
                    float v0 = (c[im][in][2 * hrow + 0] + s_tq[frl * 64 + hd]) * inv_scale;
                    float v1 = (c[im][in][2 * hrow + 1] + s_tq[frl * 64 + hd + 1]) * inv_scale;
                    stage[row * 132 + col]     = v0;
                    stage[row * 132 + col + 1] = v1;
                }
            }
        }
        __syncthreads();
        for (int cc = tid; cc < 4096; cc += 256) {
            int row = cc >> 5, ch = cc & 31;
            float4 v = *(const float4*)(stage + row * 132 + ch * 4);
            int col = ch * 4;
            int e = e0 + col;
            int h = (e >> 6) & 7, hd = col & 63;
            int grow = m0 + row;
            int b = grow >> 10, l = (grow >> 6) & 15, nt = grow & 63;
            *(float4*)(g_Q + (size_t)((b * H_ + h) * NTOK_ + l * 64 + nt) * HD_ + hd) = v;
        }
    } else {
        uint8_t* stH = (uint8_t*)smem_raw;   // [128][272B] fp16 plane
#pragma unroll
        for (int im = 0; im < 4; im++) {
#pragma unroll
            for (int hrow = 0; hrow < 2; hrow++) {
                int row = wm * 64 + im * 16 + gid + hrow * 8;
                int frl = ((m0 + row) >> 6) & 1;
#pragma unroll
                for (int in = 0; in < 4; in++) {
                    int col = wn * 32 + in * 8 + 2 * tig;
                    int hd = col & 63;
                    float v0 = c[im][in][2 * hrow + 0] + s_tq[frl * 64 + hd];
                    float v1 = c[im][in][2 * hrow + 1] + s_tq[frl * 64 + hd + 1];
                    *(uint32_t*)(stH + row * 272 + col * 2) = packh2(v0, v1);
                }
            }
        }
        __syncthreads();
        __half* dst = (third == 1) ? g_Khf : g_Vhf;
        for (int cc = tid; cc < 2048; cc += 256) {
            int row = cc >> 4, ch = cc & 15;
            int col = ch * 8;
            int e = e0 + col;
            int h = (e >> 6) & 7, hd = col & 63;
            int grow = m0 + row;
            int b = grow >> 10, l = (grow >> 6) & 15, nt = grow & 63;
            size_t off = (size_t)((b * H_ + h) * NTOK_ + l * 64 + nt) * HD_ + hd;
            *(uint4*)(dst + off) = *(const uint4*)(stH + row * 272 + ch * 16);
        }
    }
}

// ---------------------------------------------------------------------------
// Kernel 2: tensor-core fused attention, fp16 2-term scheme.
// S = (Qhi + Qlo) . Khf ;  O = (Phi + Plo) . Vhf   (K,V single fp16 plane)
// smem layout (bytes):
//   [0, 32768)      KV[2 stages][2 tiles (K,V)][8192]
//       alias init:  Qs fp32 64x68 @0 (17408), Et 16x68 @17408 (4352)
//   [32768, 40960)  Qhi fp16 64x64 swizzled
//   [40960, 49152)  Qlo
//   [49152, 53504)  bias 64x17 f32
//   [53504, 53572)  list
// ---------------------------------------------------------------------------
#define ATT_KV     0
#define ATT_QS     0
#define ATT_ET     17408
#define ATT_QHI    32768
#define ATT_QLO    (ATT_QHI + 8192)
#define ATT_BIAS   (ATT_QLO + 8192)
#define ATT_LIST   (ATT_BIAS + 64 * 17 * 4)
#define ATT_SMEM   (ATT_LIST + 68)

__global__ __launch_bounds__(128, 2) void attn_kernel(const int* __restrict__ pos,
                                                      const int* __restrict__ mask,
                                                      const float* __restrict__ emb,
                                                      float* __restrict__ out) {
    uint32_t sbase = smem_u32(smem_raw);
    float (*Qs)[68] = (float(*)[68])(smem_raw + ATT_QS);
    float (*Et)[68] = (float(*)[68])(smem_raw + ATT_ET);
    float (*bias)[17] = (float(*)[17])(smem_raw + ATT_BIAS);
    int* list = (int*)(smem_raw + ATT_LIST);

    int ql = (L_ - 1) - blockIdx.x;
    int h = blockIdx.y, b = blockIdx.z;
    int tid = threadIdx.x;
    int lane = tid & 31, w = tid >> 5;
    int r0 = w * 16;
    int bh = b * H_ + h;

    if (tid == 0) {
        int nvl = 0;
        const int* mrow = mask + (b * L_ + ql) * L_;
#pragma unroll
        for (int kl = 0; kl < L_; kl++)
            if (mrow[kl] != 0) list[nvl++] = kl;
        list[16] = nvl;
    }

    const float* Qg = g_Q + ((size_t)bh * NTOK_ + ql * 64) * HD_;
    for (int i = tid; i < 1024; i += 128) {
        int r = i >> 4, c = (i & 15) << 2;
        *(float4*)&Qs[r][c] = *(const float4*)(Qg + r * HD_ + c);
    }
    for (int i = tid; i < 1024; i += 128) {
        int kl = i >> 6, c = i & 63;
        int p = pos[(b * L_ + ql) * L_ + kl];
        p = min(max(p, -8), 8) + 8;
        Et[kl][c] = emb[p * HD_ + c];
    }
    __syncthreads();
    int nv = list[16];

#pragma unroll
    for (int u = 0; u < 8; u++) {
        int id = tid + u * 128;
        int r = id >> 4, kl = id & 15;
        float acc = 0.f;
        const float* qrow = Qs[r];
        const float* erow = Et[kl];
#pragma unroll 16
        for (int c = 0; c < 64; c++) acc += qrow[c] * erow[c];
        bias[r][kl] = acc;
    }

    // ---- convert Q -> fp16 hi/lo swizzled tiles
#pragma unroll
    for (int i = 0; i < 4; i++) {
        int linear = i * 128 + tid;
        int row = linear >> 3, ch = linear & 7;
        const float* qp = &Qs[row][ch * 8];
        uint32_t hi4[4], lo4[4];
#pragma unroll
        for (int j = 0; j < 4; j++) {
            float x0 = qp[2 * j], x1 = qp[2 * j + 1];
            __half h0 = __float2half_rn(x0), h1 = __float2half_rn(x1);
            hi4[j] = packh2(__half2float(h0), __half2float(h1));
            lo4[j] = packh2(x0 - __half2float(h0), x1 - __half2float(h1));
        }
        uint32_t soff = row * 128 + ((ch ^ (row & 7)) << 4);
        *(uint4*)(smem_raw + ATT_QHI + soff) = *(uint4*)hi4;
        *(uint4*)(smem_raw + ATT_QLO + soff) = *(uint4*)lo4;
    }
    __syncthreads();   // Qs/Et dead -> KV region free

    uint32_t qh[4][4], qlr[4][4];
    {
        int lrow = (lane & 7) + 8 * ((lane >> 3) & 1);
        int khalf = lane >> 4;
#pragma unroll
        for (int kt = 0; kt < 4; kt++) {
            int qr = r0 + lrow;
            int qc = kt * 2 + khalf;
            uint32_t off = qr * 128 + ((qc ^ (qr & 7)) << 4);
            ldsm4(qh[kt],  sbase + ATT_QHI + off);
            ldsm4(qlr[kt], sbase + ATT_QLO + off);
        }
    }

    int g4 = lane >> 2;
    float m0r = -INFINITY, m1r = -INFINITY, l0r = 0.f, l1r = 0.f;
    float O[8][4] = {};

    int klrow = (lane & 7) + 8 * (lane >> 4);
    int kchalf = (lane >> 3) & 1;
    int vlrow = (lane & 7) + 8 * ((lane >> 3) & 1);
    int vchalf = lane >> 4;

    // per-frame cp.async: 2 warps per tile (tile = w>>1: 0=K, 1=V)
    const __half* tile_src[2] = {
        g_Khf + (size_t)bh * NTOK_ * HD_, g_Vhf + (size_t)bh * NTOK_ * HD_
    };
    const __half* mysrc = tile_src[w >> 1];
    int halfw = w & 1;
    uint32_t mydst = sbase + ATT_KV + (w >> 1) * 8192;

#define ISSUE_FRAME(f, stage) do {                                              \
    const __half* _s = mysrc + (f) * 4096;                                      \
    uint32_t _d = mydst + (stage) * 16384;                                      \
    _Pragma("unroll")                                                           \
    for (int _c = 0; _c < 8; _c++) {                                            \
        int _lin = halfw * 256 + _c * 32 + lane;                                \
        int _row = _lin >> 3, _ch = _lin & 7;                                   \
        uint32_t _da = _d + _row * 128 + ((_ch ^ (_row & 7)) << 4);             \
        asm volatile("cp.async.cg.shared.global [%0], [%1], 16;"                \
                     :: "r"(_da), "l"(_s + _row * 64 + _ch * 8));               \
    }                                                                           \
    asm volatile("cp.async.commit_group;");                                     \
} while (0)

    ISSUE_FRAME(list[0], 0);

    for (int j = 0; j < nv; j++) {
        int stage = j & 1;
        if (j + 1 < nv) {
            ISSUE_FRAME(list[j + 1], (j + 1) & 1);
            asm volatile("cp.async.wait_group 1;" ::: "memory");
        } else {
            asm volatile("cp.async.wait_group 0;" ::: "memory");
        }
        __syncthreads();
        int kl = list[j];
        uint32_t khB = sbase + ATT_KV + stage * 16384;
        uint32_t vhB = khB + 8192;

        // ---- S = bias + (Qhi + Qlo).Khf  (2 fp16 MMAs per fragment)
        float S[8][4];
        float bb0 = bias[r0 + g4][kl], bb1 = bias[r0 + 8 + g4][kl];
#pragma unroll
        for (int nt = 0; nt < 8; nt++) {
            S[nt][0] = bb0; S[nt][1] = bb0; S[nt][2] = bb1; S[nt][3] = bb1;
        }
#pragma unroll
        for (int kt = 0; kt < 4; kt++) {
#pragma unroll
            for (int np = 0; np < 4; np++) {
                int nr = np * 16 + klrow;
                int kc = kt * 2 + kchalf;
                uint32_t off = nr * 128 + ((kc ^ (nr & 7)) << 4);
                uint32_t kh[4];
                ldsm4(kh, khB + off);
                mma16816h(S[2 * np],     qh[kt],  kh[0], kh[1]);
                mma16816h(S[2 * np + 1], qh[kt],  kh[2], kh[3]);
                mma16816h(S[2 * np],     qlr[kt], kh[0], kh[1]);
                mma16816h(S[2 * np + 1], qlr[kt], kh[2], kh[3]);
            }
        }

        // ---- online softmax
        float mx0 = -INFINITY, mx1 = -INFINITY;
#pragma unroll
        for (int nt = 0; nt < 8; nt++) {
            mx0 = fmaxf(mx0, fmaxf(S[nt][0], S[nt][1]));
            mx1 = fmaxf(mx1, fmaxf(S[nt][2], S[nt][3]));
        }
        mx0 = fmaxf(mx0, __shfl_xor_sync(0xffffffffu, mx0, 1));
        mx0 = fmaxf(mx0, __shfl_xor_sync(0xffffffffu, mx0, 2));
        mx1 = fmaxf(mx1, __shfl_xor_sync(0xffffffffu, mx1, 1));
        mx1 = fmaxf(mx1, __shfl_xor_sync(0xffffffffu, mx1, 2));
        float mn0 = fmaxf(m0r, mx0), mn1 = fmaxf(m1r, mx1);
        float corr0 = __expf(m0r - mn0), corr1 = __expf(m1r - mn1);
        float sum0 = 0.f, sum1 = 0.f;
#pragma unroll
        for (int nt = 0; nt < 8; nt++) {
            S[nt][0] = __expf(S[nt][0] - mn0); S[nt][1] = __expf(S[nt][1] - mn0);
            S[nt][2] = __expf(S[nt][2] - mn1); S[nt][3] = __expf(S[nt][3] - mn1);
            sum0 += S[nt][0] + S[nt][1];
            sum1 += S[nt][2] + S[nt][3];
        }
        sum0 += __shfl_xor_sync(0xffffffffu, sum0, 1);
        sum0 += __shfl_xor_sync(0xffffffffu, sum0, 2);
        sum1 += __shfl_xor_sync(0xffffffffu, sum1, 1);
        sum1 += __shfl_xor_sync(0xffffffffu, sum1, 2);
        l0r = l0r * corr0 + sum0; m0r = mn0;
        l1r = l1r * corr1 + sum1; m1r = mn1;

        // ---- P fp16 hi/lo A-fragments
        uint32_t ph[4][4], pl[4][4];
#pragma unroll
        for (int kt = 0; kt < 4; kt++) {
#pragma unroll
            for (int q = 0; q < 4; q++) {
                int nt = 2 * kt + (q >> 1);
                float x0 = S[nt][(q & 1) * 2], x1 = S[nt][(q & 1) * 2 + 1];
                __half hx0 = __float2half_rn(x0), hx1 = __float2half_rn(x1);
                ph[kt][q] = packh2(__half2float(hx0), __half2float(hx1));
                pl[kt][q] = packh2(x0 - __half2float(hx0), x1 - __half2float(hx1));
            }
        }

        // ---- O = O*corr + (Phi + Plo).Vhf
#pragma unroll
        for (int nt = 0; nt < 8; nt++) {
            O[nt][0] *= corr0; O[nt][1] *= corr0; O[nt][2] *= corr1; O[nt][3] *= corr1;
        }
#pragma unroll
        for (int kt = 0; kt < 4; kt++) {
#pragma unroll
            for (int np = 0; np < 4; np++) {
                int vr = kt * 16 + vlrow;
                int vc = np * 2 + vchalf;
                uint32_t off = vr * 128 + ((vc ^ (vr & 7)) << 4);
                uint32_t vh[4];
                ldsm4t(vh, vhB + off);
                mma16816h(O[2 * np],     ph[kt], vh[0], vh[1]);
                mma16816h(O[2 * np + 1], ph[kt], vh[2], vh[3]);
                mma16816h(O[2 * np],     pl[kt], vh[0], vh[1]);
                mma16816h(O[2 * np + 1], pl[kt], vh[2], vh[3]);
            }
        }
        __syncthreads();
    }

    // ---- stage normalized O, coalesced store
    {
        float inv0 = 1.f / l0r, inv1 = 1.f / l1r;
        float* stage = (float*)smem_raw;   // KV region free
        int cl = 2 * (lane & 3);
#pragma unroll
        for (int nt = 0; nt < 8; nt++) {
            stage[(r0 + g4) * 68 + nt * 8 + cl]         = O[nt][0] * inv0;
            stage[(r0 + g4) * 68 + nt * 8 + cl + 1]     = O[nt][1] * inv0;
            stage[(r0 + 8 + g4) * 68 + nt * 8 + cl]     = O[nt][2] * inv1;
            stage[(r0 + 8 + g4) * 68 + nt * 8 + cl + 1] = O[nt][3] * inv1;
        }
        __syncthreads();
        for (int cc = tid; cc < 1024; cc += 128) {
            int row = cc >> 4, ch = cc & 15;
            float4 v = *(const float4*)(stage + row * 68 + ch * 4);
            *(float4*)(out + (size_t)((b * L_ + ql) * 64 + row) * D_ + h * HD_ + ch * 4) = v;
        }
    }
}

// ---------------------------------------------------------------------------
extern "C" void kernel_launch(void* const* d_in, const int* in_sizes, int n_in,
                              void* d_out, int out_size) {
    const float* x    = (const float*)d_in[0];
    const float* te   = (const float*)d_in[1];
    const int*   pos  = (const int*)d_in[2];
    const int*   mask = (const int*)d_in[3];
    const float* Wqkv = (const float*)d_in[4];
    const float* Wt   = (const float*)d_in[5];
    const float* emb  = (const float*)d_in[6];
    float* out = (float*)d_out;

    cudaFuncSetAttribute(qkv_gemm, cudaFuncAttributeMaxDynamicSharedMemorySize, GEMM_SMEM);
    cudaFuncSetAttribute(attn_kernel, cudaFuncAttributeMaxDynamicSharedMemorySize, ATT_SMEM);

    split_kernel<<<(XQUADS + WQUADS) / 256, 256>>>(x, Wqkv);
    qkv_gemm<<<dim3(E3_ / 128, 4096 / 128), 256, GEMM_SMEM>>>(te, Wt);
    attn_kernel<<<dim3(L_, H_, B_), 128, ATT_SMEM>>>(pos, mask, emb, out);
}

// round 13
// speedup vs baseline: 2.2596x; 1.3593x over previous
#include <cuda_runtime.h>
#include <cuda_fp16.h>
#include <math.h>
#include <stdint.h>

#define B_    4
#define L_    16
#define D_    512
#define H_    8
#define HD_   64
#define NTOK_ 1024
#define E3_   1536

// Scratch (allocation-free rule: __device__ globals)
__device__ float g_Q[B_ * H_ * NTOK_ * HD_];
__device__ __half g_Khf[B_ * H_ * NTOK_ * HD_];
__device__ __half g_Vhf[B_ * H_ * NTOK_ * HD_];
__device__ __half g_Xhf[4096 * 512];
__device__ __half g_Whf[1536 * 512];

__device__ __forceinline__ uint32_t smem_u32(const void* p) {
    uint32_t a;
    asm("{ .reg .u64 t; cvta.to.shared.u64 t, %1; cvt.u32.u64 %0, t; }" : "=r"(a) : "l"(p));
    return a;
}
__device__ __forceinline__ void ldsm4(uint32_t* r, uint32_t addr) {
    asm volatile("ldmatrix.sync.aligned.m8n8.x4.shared.b16 {%0,%1,%2,%3}, [%4];"
        : "=r"(r[0]), "=r"(r[1]), "=r"(r[2]), "=r"(r[3]) : "r"(addr));
}
__device__ __forceinline__ void ldsm4t(uint32_t* r, uint32_t addr) {
    asm volatile("ldmatrix.sync.aligned.m8n8.x4.trans.shared.b16 {%0,%1,%2,%3}, [%4];"
        : "=r"(r[0]), "=r"(r[1]), "=r"(r[2]), "=r"(r[3]) : "r"(addr));
}
__device__ __forceinline__ void mma16816h(float* c, const uint32_t* a, uint32_t b0, uint32_t b1) {
    asm volatile("mma.sync.aligned.m16n8k16.row.col.f32.f16.f16.f32 "
        "{%0,%1,%2,%3}, {%4,%5,%6,%7}, {%8,%9}, {%0,%1,%2,%3};"
        : "+f"(c[0]), "+f"(c[1]), "+f"(c[2]), "+f"(c[3])
        : "r"(a[0]), "r"(a[1]), "r"(a[2]), "r"(a[3]), "r"(b0), "r"(b1));
}
__device__ __forceinline__ uint32_t packh2(float a, float b) {
    __half2 t = __floats2half2_rn(a, b);
    return *reinterpret_cast<uint32_t*>(&t);
}

extern __shared__ char smem_raw[];

// ---------------------------------------------------------------------------
// Kernel 0: convert X and W to fp16 (single plane).
// ---------------------------------------------------------------------------
#define XQUADS 524288   // 4096*512/4
#define WQUADS 196608   // 1536*512/4

__global__ __launch_bounds__(256) void split_kernel(const float* __restrict__ x,
                                                    const float* __restrict__ W) {
    int i = blockIdx.x * 256 + threadIdx.x;
    const float4* src;
    __half2* hp;
    int idx;
    if (i < XQUADS) { src = (const float4*)x; hp = (__half2*)g_Xhf; idx = i; }
    else            { src = (const float4*)W; hp = (__half2*)g_Whf; idx = i - XQUADS; }
    float4 v = src[idx];
    hp[idx * 2 + 0] = __floats2half2_rn(v.x, v.y);
    hp[idx * 2 + 1] = __floats2half2_rn(v.z, v.w);
}

// ---------------------------------------------------------------------------
// Kernel 1: QKV GEMM via fp16 mma.sync, K = 512 single plane.
// 6-stage cp.async ring, 2 chunks/barrier, 8 iterations.
// Epilogue: Q -> fp32 (pre-scaled); K,V -> fp16.
// ---------------------------------------------------------------------------
#define GEMM_SMEM (12 * 8192 + 512)

__global__ __launch_bounds__(256, 2) void qkv_gemm(const float* __restrict__ te,
                                                   const float* __restrict__ Wt) {
    uint32_t aBase = smem_u32(smem_raw);
    uint32_t bBase = aBase + 6 * 8192;
    float* s_tq = (float*)(smem_raw + 12 * 8192);

    int tid = threadIdx.x;
    int m0 = blockIdx.y * 128, e0 = blockIdx.x * 128;
    int bb = m0 >> 10, l0 = (m0 >> 6) & 15, third = e0 >> 9;

    int mld = tid >> 1;
    int kc0 = (tid & 1) * 2;
    int swm = (mld >> 1) & 3;
    uint32_t dA0 = aBase + mld * 64, dB0 = bBase + mld * 64;
    const __half* Asrc = g_Xhf + (size_t)(m0 + mld) * 512;
    const __half* Bsrc = g_Whf + (size_t)(e0 + mld) * 512;

#define ISSUE(ki, st) do {                                                      \
    int _kb = (ki) * 32;                                                        \
    _Pragma("unroll")                                                           \
    for (int _j = 0; _j < 2; _j++) {                                            \
        int _kc = kc0 + _j;                                                     \
        const void* _sa = Asrc + _kb + _kc * 8;                                 \
        const void* _sb = Bsrc + _kb + _kc * 8;                                 \
        uint32_t _da = dA0 + (st) * 8192 + (((_kc) ^ swm) << 4);                \
        uint32_t _db = dB0 + (st) * 8192 + (((_kc) ^ swm) << 4);                \
        asm volatile("cp.async.cg.shared.global [%0], [%1], 16;" :: "r"(_da), "l"(_sa)); \
        asm volatile("cp.async.cg.shared.global [%0], [%1], 16;" :: "r"(_db), "l"(_sb)); \
    }                                                                           \
    asm volatile("cp.async.commit_group;");                                     \
} while (0)

    ISSUE(0, 0);
    ISSUE(1, 1);
    ISSUE(2, 2);
    ISSUE(3, 3);

    // in-block tqkv overlaps with prefetch latency (fp32)
    {
        int outi = tid >> 1, half = tid & 1;
        int fr = outi >> 6, hd = outi & 63;
        const float4* tp = (const float4*)(te + (size_t)(bb * 16 + l0 + fr) * D_) + half * 64;
        const float4* wp = (const float4*)(Wt + (size_t)(third * 64 + hd) * D_) + half * 64;
        float acc = 0.f;
#pragma unroll 8
        for (int k = 0; k < 64; k++) {
            float4 a = tp[k], w = wp[k];
            acc += a.x * w.x + a.y * w.y + a.z * w.z + a.w * w.w;
        }
        acc += __shfl_xor_sync(0xffffffffu, acc, 1);
        if (!half) s_tq[outi] = acc;
    }

    int lane = tid & 31, warp = tid >> 5;
    int wm = warp & 1, wn = warp >> 1;
    uint32_t aAddr[4]; int aXor[4];
    int rA = lane & 15, kcbA = lane >> 4;
#pragma unroll
    for (int im = 0; im < 4; im++) {
        int mr = wm * 64 + im * 16 + rA;
        aAddr[im] = aBase + mr * 64;
        aXor[im] = (mr >> 1) & 3;
    }
    uint32_t bAddr[2]; int bXor[2];
    int kcbB = (lane >> 3) & 1;
#pragma unroll
    for (int p = 0; p < 2; p++) {
        int nr = wn * 32 + p * 16 + (lane & 7) + ((lane >> 4) << 3);
        bAddr[p] = bBase + nr * 64;
        bXor[p] = (nr >> 1) & 3;
    }

    float c[4][4][4] = {};

    for (int it = 0; it < 8; it++) {
        if (it < 7) {
            asm volatile("cp.async.wait_group 2;" ::: "memory");
        } else {
            asm volatile("cp.async.wait_group 0;" ::: "memory");
        }
        __syncthreads();
        int k0 = 2 * it;
        if (k0 + 4 < 16) ISSUE(k0 + 4, (k0 + 4) % 6);
        if (k0 + 5 < 16) ISSUE(k0 + 5, (k0 + 5) % 6);
#pragma unroll
        for (int half = 0; half < 2; half++) {
            int cur = (k0 + half) % 6;
#pragma unroll
            for (int s = 0; s < 2; s++) {
                uint32_t a[4][4];
#pragma unroll
                for (int im = 0; im < 4; im++)
                    ldsm4(a[im], aAddr[im] + cur * 8192 + (((kcbA + 2 * s) ^ aXor[im]) << 4));
                uint32_t bq[2][4];
#pragma unroll
                for (int p = 0; p < 2; p++)
                    ldsm4(bq[p], bAddr[p] + cur * 8192 + (((kcbB + 2 * s) ^ bXor[p]) << 4));
#pragma unroll
                for (int im = 0; im < 4; im++)
#pragma unroll
                    for (int in = 0; in < 4; in++)
                        mma16816h(c[im][in], a[im], bq[in >> 1][(in & 1) * 2], bq[in >> 1][(in & 1) * 2 + 1]);
            }
        }
    }

    // ---- coalesced smem-staged epilogue ----
    __syncthreads();
    const float inv_scale = 0.044194173824159216f;  // 1/sqrt(512)
    int gid = lane >> 2, tig = lane & 3;

    if (third == 0) {
        float* stage = (float*)smem_raw;   // [128][132] fp32
#pragma unroll
        for (int im = 0; im < 4; im++) {
#pragma unroll
            for (int hrow = 0; hrow < 2; hrow++) {
                int row = wm * 64 + im * 16 + gid + hrow * 8;
                int frl = ((m0 + row) >> 6) & 1;
#pragma unroll
                for (int in = 0; in < 4; in++) {
                    int col = wn * 32 + in * 8 + 2 * tig;
                    int hd = col & 63;
                    float v0 = (c[im][in][2 * hrow + 0] + s_tq[frl * 64 + hd]) * inv_scale;
                    float v1 = (c[im][in][2 * hrow + 1] + s_tq[frl * 64 + hd + 1]) * inv_scale;
                    stage[row * 132 + col]     = v0;
                    stage[row * 132 + col + 1] = v1;
                }
            }
        }
        __syncthreads();
        for (int cc = tid; cc < 4096; cc += 256) {
            int row = cc >> 5, ch = cc & 31;
            float4 v = *(const float4*)(stage + row * 132 + ch * 4);
            int col = ch * 4;
            int e = e0 + col;
            int h = (e >> 6) & 7, hd = col & 63;
            int grow = m0 + row;
            int b = grow >> 10, l = (grow >> 6) & 15, nt = grow & 63;
            *(float4*)(g_Q + (size_t)((b * H_ + h) * NTOK_ + l * 64 + nt) * HD_ + hd) = v;
        }
    } else {
        uint8_t* stH = (uint8_t*)smem_raw;   // [128][272B] fp16 plane
#pragma unroll
        for (int im = 0; im < 4; im++) {
#pragma unroll
            for (int hrow = 0; hrow < 2; hrow++) {
                int row = wm * 64 + im * 16 + gid + hrow * 8;
                int frl = ((m0 + row) >> 6) & 1;
#pragma unroll
                for (int in = 0; in < 4; in++) {
                    int col = wn * 32 + in * 8 + 2 * tig;
                    int hd = col & 63;
                    float v0 = c[im][in][2 * hrow + 0] + s_tq[frl * 64 + hd];
                    float v1 = c[im][in][2 * hrow + 1] + s_tq[frl * 64 + hd + 1];
                    *(uint32_t*)(stH + row * 272 + col * 2) = packh2(v0, v1);
                }
            }
        }
        __syncthreads();
        __half* dst = (third == 1) ? g_Khf : g_Vhf;
        for (int cc = tid; cc < 2048; cc += 256) {
            int row = cc >> 4, ch = cc & 15;
            int col = ch * 8;
            int e = e0 + col;
            int h = (e >> 6) & 7, hd = col & 63;
            int grow = m0 + row;
            int b = grow >> 10, l = (grow >> 6) & 15, nt = grow & 63;
            size_t off = (size_t)((b * H_ + h) * NTOK_ + l * 64 + nt) * HD_ + hd;
            *(uint4*)(dst + off) = *(const uint4*)(stH + row * 272 + ch * 16);
        }
    }
}

// ---------------------------------------------------------------------------
// Kernel 2: tensor-core fused attention, pure fp16 single-plane.
// S = Qhf . Khf ;  O = Phf . Vhf
// smem layout (bytes):
//   [0, 32768)      KV[2 stages][2 tiles (K,V)][8192]
//       alias init:  Qs fp32 64x68 @0 (17408), Et 16x68 @17408 (4352)
//   [32768, 40960)  Qhf fp16 64x64 swizzled
//   [40960, 45312)  bias 64x17 f32
//   [45312, 45380)  list
// ---------------------------------------------------------------------------
#define ATT_KV     0
#define ATT_QS     0
#define ATT_ET     17408
#define ATT_QHF    32768
#define ATT_BIAS   (ATT_QHF + 8192)
#define ATT_LIST   (ATT_BIAS + 64 * 17 * 4)
#define ATT_SMEM   (ATT_LIST + 68)

__global__ __launch_bounds__(128, 2) void attn_kernel(const int* __restrict__ pos,
                                                      const int* __restrict__ mask,
                                                      const float* __restrict__ emb,
                                                      float* __restrict__ out) {
    uint32_t sbase = smem_u32(smem_raw);
    float (*Qs)[68] = (float(*)[68])(smem_raw + ATT_QS);
    float (*Et)[68] = (float(*)[68])(smem_raw + ATT_ET);
    float (*bias)[17] = (float(*)[17])(smem_raw + ATT_BIAS);
    int* list = (int*)(smem_raw + ATT_LIST);

    int ql = (L_ - 1) - blockIdx.x;
    int h = blockIdx.y, b = blockIdx.z;
    int tid = threadIdx.x;
    int lane = tid & 31, w = tid >> 5;
    int r0 = w * 16;
    int bh = b * H_ + h;

    if (tid == 0) {
        int nvl = 0;
        const int* mrow = mask + (b * L_ + ql) * L_;
#pragma unroll
        for (int kl = 0; kl < L_; kl++)
            if (mrow[kl] != 0) list[nvl++] = kl;
        list[16] = nvl;
    }

    const float* Qg = g_Q + ((size_t)bh * NTOK_ + ql * 64) * HD_;
    for (int i = tid; i < 1024; i += 128) {
        int r = i >> 4, c = (i & 15) << 2;
        *(float4*)&Qs[r][c] = *(const float4*)(Qg + r * HD_ + c);
    }
    for (int i = tid; i < 1024; i += 128) {
        int kl = i >> 6, c = i & 63;
        int p = pos[(b * L_ + ql) * L_ + kl];
        p = min(max(p, -8), 8) + 8;
        Et[kl][c] = emb[p * HD_ + c];
    }
    __syncthreads();
    int nv = list[16];

#pragma unroll
    for (int u = 0; u < 8; u++) {
        int id = tid + u * 128;
        int r = id >> 4, kl = id & 15;
        float acc = 0.f;
        const float* qrow = Qs[r];
        const float* erow = Et[kl];
#pragma unroll 16
        for (int c = 0; c < 64; c++) acc += qrow[c] * erow[c];
        bias[r][kl] = acc;
    }

    // ---- convert Q -> fp16 swizzled tile
#pragma unroll
    for (int i = 0; i < 4; i++) {
        int linear = i * 128 + tid;
        int row = linear >> 3, ch = linear & 7;
        const float* qp = &Qs[row][ch * 8];
        uint32_t hi4[4];
#pragma unroll
        for (int j = 0; j < 4; j++)
            hi4[j] = packh2(qp[2 * j], qp[2 * j + 1]);
        uint32_t soff = row * 128 + ((ch ^ (row & 7)) << 4);
        *(uint4*)(smem_raw + ATT_QHF + soff) = *(uint4*)hi4;
    }
    __syncthreads();   // Qs/Et dead -> KV region free

    uint32_t qh[4][4];
    {
        int lrow = (lane & 7) + 8 * ((lane >> 3) & 1);
        int khalf = lane >> 4;
#pragma unroll
        for (int kt = 0; kt < 4; kt++) {
            int qr = r0 + lrow;
            int qc = kt * 2 + khalf;
            uint32_t off = qr * 128 + ((qc ^ (qr & 7)) << 4);
            ldsm4(qh[kt], sbase + ATT_QHF + off);
        }
    }

    int g4 = lane >> 2;
    float m0r = -INFINITY, m1r = -INFINITY, l0r = 0.f, l1r = 0.f;
    float O[8][4] = {};

    int klrow = (lane & 7) + 8 * (lane >> 4);
    int kchalf = (lane >> 3) & 1;
    int vlrow = (lane & 7) + 8 * ((lane >> 3) & 1);
    int vchalf = lane >> 4;

    // per-frame cp.async: 2 warps per tile (tile = w>>1: 0=K, 1=V)
    const __half* tile_src[2] = {
        g_Khf + (size_t)bh * NTOK_ * HD_, g_Vhf + (size_t)bh * NTOK_ * HD_
    };
    const __half* mysrc = tile_src[w >> 1];
    int halfw = w & 1;
    uint32_t mydst = sbase + ATT_KV + (w >> 1) * 8192;

#define ISSUE_FRAME(f, stage) do {                                              \
    const __half* _s = mysrc + (f) * 4096;                                      \
    uint32_t _d = mydst + (stage) * 16384;                                      \
    _Pragma("unroll")                                                           \
    for (int _c = 0; _c < 8; _c++) {                                            \
        int _lin = halfw * 256 + _c * 32 + lane;                                \
        int _row = _lin >> 3, _ch = _lin & 7;                                   \
        uint32_t _da = _d + _row * 128 + ((_ch ^ (_row & 7)) << 4);             \
        asm volatile("cp.async.cg.shared.global [%0], [%1], 16;"                \
                     :: "r"(_da), "l"(_s + _row * 64 + _ch * 8));               \
    }                                                                           \
    asm volatile("cp.async.commit_group;");                                     \
} while (0)

    ISSUE_FRAME(list[0], 0);

    for (int j = 0; j < nv; j++) {
        int stage = j & 1;
        if (j + 1 < nv) {
            ISSUE_FRAME(list[j + 1], (j + 1) & 1);
            asm volatile("cp.async.wait_group 1;" ::: "memory");
        } else {
            asm volatile("cp.async.wait_group 0;" ::: "memory");
        }
        __syncthreads();
        int kl = list[j];
        uint32_t khB = sbase + ATT_KV + stage * 16384;
        uint32_t vhB = khB + 8192;

        // ---- S = bias + Qhf.Khf
        float S[8][4];
        float bb0 = bias[r0 + g4][kl], bb1 = bias[r0 + 8 + g4][kl];
#pragma unroll
        for (int nt = 0; nt < 8; nt++) {
            S[nt][0] = bb0; S[nt][1] = bb0; S[nt][2] = bb1; S[nt][3] = bb1;
        }
#pragma unroll
        for (int kt = 0; kt < 4; kt++) {
#pragma unroll
            for (int np = 0; np < 4; np++) {
                int nr = np * 16 + klrow;
                int kc = kt * 2 + kchalf;
                uint32_t off = nr * 128 + ((kc ^ (nr & 7)) << 4);
                uint32_t kh[4];
                ldsm4(kh, khB + off);
                mma16816h(S[2 * np],     qh[kt], kh[0], kh[1]);
                mma16816h(S[2 * np + 1], qh[kt], kh[2], kh[3]);
            }
        }

        // ---- online softmax
        float mx0 = -INFINITY, mx1 = -INFINITY;
#pragma unroll
        for (int nt = 0; nt < 8; nt++) {
            mx0 = fmaxf(mx0, fmaxf(S[nt][0], S[nt][1]));
            mx1 = fmaxf(mx1, fmaxf(S[nt][2], S[nt][3]));
        }
        mx0 = fmaxf(mx0, __shfl_xor_sync(0xffffffffu, mx0, 1));
        mx0 = fmaxf(mx0, __shfl_xor_sync(0xffffffffu, mx0, 2));
        mx1 = fmaxf(mx1, __shfl_xor_sync(0xffffffffu, mx1, 1));
        mx1 = fmaxf(mx1, __shfl_xor_sync(0xffffffffu, mx1, 2));
        float mn0 = fmaxf(m0r, mx0), mn1 = fmaxf(m1r, mx1);
        float corr0 = __expf(m0r - mn0), corr1 = __expf(m1r - mn1);
        float sum0 = 0.f, sum1 = 0.f;
#pragma unroll
        for (int nt = 0; nt < 8; nt++) {
            S[nt][0] = __expf(S[nt][0] - mn0); S[nt][1] = __expf(S[nt][1] - mn0);
            S[nt][2] = __expf(S[nt][2] - mn1); S[nt][3] = __expf(S[nt][3] - mn1);
            sum0 += S[nt][0] + S[nt][1];
            sum1 += S[nt][2] + S[nt][3];
        }
        sum0 += __shfl_xor_sync(0xffffffffu, sum0, 1);
        sum0 += __shfl_xor_sync(0xffffffffu, sum0, 2);
        sum1 += __shfl_xor_sync(0xffffffffu, sum1, 1);
        sum1 += __shfl_xor_sync(0xffffffffu, sum1, 2);
        l0r = l0r * corr0 + sum0; m0r = mn0;
        l1r = l1r * corr1 + sum1; m1r = mn1;

        // ---- P fp16 A-fragments
        uint32_t ph[4][4];
#pragma unroll
        for (int kt = 0; kt < 4; kt++) {
#pragma unroll
            for (int q = 0; q < 4; q++) {
                int nt = 2 * kt + (q >> 1);
                ph[kt][q] = packh2(S[nt][(q & 1) * 2], S[nt][(q & 1) * 2 + 1]);
            }
        }

        // ---- O = O*corr + Phf.Vhf
#pragma unroll
        for (int nt = 0; nt < 8; nt++) {
            O[nt][0] *= corr0; O[nt][1] *= corr0; O[nt][2] *= corr1; O[nt][3] *= corr1;
        }
#pragma unroll
        for (int kt = 0; kt < 4; kt++) {
#pragma unroll
            for (int np = 0; np < 4; np++) {
                int vr = kt * 16 + vlrow;
                int vc = np * 2 + vchalf;
                uint32_t off = vr * 128 + ((vc ^ (vr & 7)) << 4);
                uint32_t vh[4];
                ldsm4t(vh, vhB + off);
                mma16816h(O[2 * np],     ph[kt], vh[0], vh[1]);
                mma16816h(O[2 * np + 1], ph[kt], vh[2], vh[3]);
            }
        }
        __syncthreads();
    }

    // ---- stage normalized O, coalesced store
    {
        float inv0 = 1.f / l0r, inv1 = 1.f / l1r;
        float* stage = (float*)smem_raw;   // KV region free
        int cl = 2 * (lane & 3);
#pragma unroll
        for (int nt = 0; nt < 8; nt++) {
            stage[(r0 + g4) * 68 + nt * 8 + cl]         = O[nt][0] * inv0;
            stage[(r0 + g4) * 68 + nt * 8 + cl + 1]     = O[nt][1] * inv0;
            stage[(r0 + 8 + g4) * 68 + nt * 8 + cl]     = O[nt][2] * inv1;
            stage[(r0 + 8 + g4) * 68 + nt * 8 + cl + 1] = O[nt][3] * inv1;
        }
        __syncthreads();
        for (int cc = tid; cc < 1024; cc += 128) {
            int row = cc >> 4, ch = cc & 15;
            float4 v = *(const float4*)(stage + row * 68 + ch * 4);
            *(float4*)(out + (size_t)((b * L_ + ql) * 64 + row) * D_ + h * HD_ + ch * 4) = v;
        }
    }
}

// ---------------------------------------------------------------------------
extern "C" void kernel_launch(void* const* d_in, const int* in_sizes, int n_in,
                              void* d_out, int out_size) {
    const float* x    = (const float*)d_in[0];
    const float* te   = (const float*)d_in[1];
    const int*   pos  = (const int*)d_in[2];
    const int*   mask = (const int*)d_in[3];
    const float* Wqkv = (const float*)d_in[4];
    const float* Wt   = (const float*)d_in[5];
    const float* emb  = (const float*)d_in[6];
    float* out = (float*)d_out;

    cudaFuncSetAttribute(qkv_gemm, cudaFuncAttributeMaxDynamicSharedMemorySize, GEMM_SMEM);
    cudaFuncSetAttribute(attn_kernel, cudaFuncAttributeMaxDynamicSharedMemorySize, ATT_SMEM);

    split_kernel<<<(XQUADS + WQUADS) / 256, 256>>>(x, Wqkv);
    qkv_gemm<<<dim3(E3_ / 128, 4096 / 128), 256, GEMM_SMEM>>>(te, Wt);
    attn_kernel<<<dim3(L_, H_, B_), 128, ATT_SMEM>>>(pos, mask, emb, out);
}